// round 2
// baseline (speedup 1.0000x reference)
#include <cuda_runtime.h>
#include <cuda_bf16.h>
#include <math.h>

// ---------------------------------------------------------------------------
// Problem constants
// ---------------------------------------------------------------------------
#define NB   4
#define LL   4096
#define SS   4096
#define CC   512
#define NH   8
#define HD   64
#define C2   1024
#define NTOK (NB * LL)          // 16384
#define EPS_Z 1e-6f
#define LN_EPS 1e-5f

// ---------------------------------------------------------------------------
// Scratch (device globals; no allocation allowed)
// ---------------------------------------------------------------------------
__device__ float g_Q  [(size_t)NTOK * CC];   // feature-mapped Q projection
__device__ float g_K  [(size_t)NTOK * CC];   // feature-mapped K projection
__device__ float g_V  [(size_t)NTOK * CC];   // V projection (scaled by 1/S)
__device__ float g_KV [NB * NH * HD * HD];   // per-(n,h) K^T V
__device__ float g_Ks [NB * NH * HD];        // per-(n,h) sum_s K
__device__ float g_Msg[(size_t)NTOK * CC];   // attention message (pre Wm)
__device__ float g_M1 [(size_t)NTOK * CC];   // message @ Wm^T
__device__ float g_H0 [(size_t)NTOK * C2];   // concat(x, LN(M1))
__device__ float g_H1 [(size_t)NTOK * C2];   // relu(H0 @ W1^T)
__device__ float g_M2 [(size_t)NTOK * CC];   // H1 @ W2^T

// ---------------------------------------------------------------------------
// Tiled SGEMM: C[m,n] = epi( scale * sum_k A[m,k] * B[n,k] )
// A: [M,K] row-major, B: [N,K] row-major (i.e., torch Linear weight), C: [M,N]
// M % 128 == 0, N % 128 == 0, K % 16 == 0 (all true here).
// EPI: 0 = identity, 1 = elu+1 feature map, 2 = relu
// ---------------------------------------------------------------------------
#define BM 128
#define BN 128
#define BK 16
#define TM 8
#define TN 8

template <int EPI>
__global__ void __launch_bounds__(256)
sgemm_nt(const float* __restrict__ A, const float* __restrict__ B,
         float* __restrict__ C, int M, int N, int K, float scale)
{
    __shared__ float As[BK][BM];
    __shared__ float Bs[BK][BN];

    const int tid = threadIdx.x;
    const int tx  = tid & 15;        // 0..15  -> N micro-tile
    const int ty  = tid >> 4;        // 0..15  -> M micro-tile
    const int bx  = blockIdx.x;      // N tile
    const int by  = blockIdx.y;      // M tile

    const float* Ab = A + (size_t)by * BM * K;
    const float* Bb = B + (size_t)bx * BN * K;

    const int lr = tid >> 2;         // 0..63 (row within half-tile)
    const int lc = (tid & 3) * 4;    // 0,4,8,12

    float acc[TM][TN];
#pragma unroll
    for (int i = 0; i < TM; i++)
#pragma unroll
        for (int j = 0; j < TN; j++) acc[i][j] = 0.f;

    for (int k0 = 0; k0 < K; k0 += BK) {
#pragma unroll
        for (int rr = 0; rr < 2; rr++) {
            const int row = lr + rr * 64;
            float4 va = *(const float4*)(Ab + (size_t)row * K + k0 + lc);
            As[lc + 0][row] = va.x;
            As[lc + 1][row] = va.y;
            As[lc + 2][row] = va.z;
            As[lc + 3][row] = va.w;
            float4 vb = *(const float4*)(Bb + (size_t)row * K + k0 + lc);
            Bs[lc + 0][row] = vb.x;
            Bs[lc + 1][row] = vb.y;
            Bs[lc + 2][row] = vb.z;
            Bs[lc + 3][row] = vb.w;
        }
        __syncthreads();

#pragma unroll
        for (int kk = 0; kk < BK; kk++) {
            float a[TM], b[TN];
#pragma unroll
            for (int i = 0; i < TM; i++) a[i] = As[kk][ty * TM + i];
#pragma unroll
            for (int j = 0; j < TN; j++) b[j] = Bs[kk][tx * TN + j];
#pragma unroll
            for (int i = 0; i < TM; i++)
#pragma unroll
                for (int j = 0; j < TN; j++) acc[i][j] = fmaf(a[i], b[j], acc[i][j]);
        }
        __syncthreads();
    }

    float* Cb = C + (size_t)(by * BM + ty * TM) * N + bx * BN + tx * TN;
#pragma unroll
    for (int i = 0; i < TM; i++) {
#pragma unroll
        for (int j = 0; j < TN; j++) {
            float v = acc[i][j] * scale;
            if (EPI == 1) v = (v > 0.f) ? (v + 1.f) : expf(v);   // elu(v)+1
            if (EPI == 2) v = fmaxf(v, 0.f);
            Cb[(size_t)i * N + j] = v;
        }
    }
}

// ---------------------------------------------------------------------------
// Zero KV / Ksum accumulators
// ---------------------------------------------------------------------------
__global__ void zero_kv_kernel()
{
    int i = blockIdx.x * blockDim.x + threadIdx.x;
    if (i < NB * NH * HD * HD) g_KV[i] = 0.f;
    if (i < NB * NH * HD)      g_Ks[i] = 0.f;
}

// ---------------------------------------------------------------------------
// KV[n,h,d,v] = sum_s K[n,s,h,d] * V[n,s,h,v] ; Ksum[n,h,d] = sum_s K[n,s,h,d]
// grid: (SPLIT, NH, NB), block 256. Each block handles SS/SPLIT s-rows,
// accumulates a full 64x64 in registers (4x4 per thread), atomically adds.
// ---------------------------------------------------------------------------
#define KV_SPLIT 16
__global__ void __launch_bounds__(256)
kv_kernel()
{
    const int n = blockIdx.z, h = blockIdx.y, sp = blockIdx.x;
    const int SPS = SS / KV_SPLIT;        // 256
    const int s0  = sp * SPS;

    __shared__ float Ksm[16][HD];
    __shared__ float Vsm[16][HD];

    const int tid = threadIdx.x;
    const int d0  = (tid >> 4) * 4;       // 0..60
    const int v0  = (tid & 15) * 4;       // 0..60
    const int lr  = tid >> 4;             // 0..15 row
    const int lq  = (tid & 15) * 4;       // 0..60 col group

    float acc[4][4];
#pragma unroll
    for (int i = 0; i < 4; i++)
#pragma unroll
        for (int j = 0; j < 4; j++) acc[i][j] = 0.f;
    float ksacc[4] = {0.f, 0.f, 0.f, 0.f};

    for (int sc = 0; sc < SPS; sc += 16) {
        const size_t base = ((size_t)(n * SS + s0 + sc + lr)) * CC + h * HD + lq;
        float4 kv4 = *(const float4*)(g_K + base);
        Ksm[lr][lq + 0] = kv4.x; Ksm[lr][lq + 1] = kv4.y;
        Ksm[lr][lq + 2] = kv4.z; Ksm[lr][lq + 3] = kv4.w;
        float4 vv4 = *(const float4*)(g_V + base);
        Vsm[lr][lq + 0] = vv4.x; Vsm[lr][lq + 1] = vv4.y;
        Vsm[lr][lq + 2] = vv4.z; Vsm[lr][lq + 3] = vv4.w;
        __syncthreads();

#pragma unroll
        for (int s = 0; s < 16; s++) {
            float a[4], b[4];
#pragma unroll
            for (int i = 0; i < 4; i++) a[i] = Ksm[s][d0 + i];
#pragma unroll
            for (int j = 0; j < 4; j++) b[j] = Vsm[s][v0 + j];
#pragma unroll
            for (int i = 0; i < 4; i++)
#pragma unroll
                for (int j = 0; j < 4; j++) acc[i][j] = fmaf(a[i], b[j], acc[i][j]);
            if (v0 == 0) {
#pragma unroll
                for (int i = 0; i < 4; i++) ksacc[i] += a[i];
            }
        }
        __syncthreads();
    }

    float* KVp = g_KV + (size_t)(n * NH + h) * HD * HD;
#pragma unroll
    for (int i = 0; i < 4; i++)
#pragma unroll
        for (int j = 0; j < 4; j++)
            atomicAdd(&KVp[(d0 + i) * HD + v0 + j], acc[i][j]);
    if (v0 == 0) {
        float* Kp = g_Ks + (n * NH + h) * HD;
#pragma unroll
        for (int i = 0; i < 4; i++) atomicAdd(&Kp[d0 + i], ksacc[i]);
    }
}

// ---------------------------------------------------------------------------
// message[n,l,h,v] = S * (sum_d Q[n,l,h,d] * KV[n,h,d,v]) / (Q . Ksum + eps)
// grid: (LL/64, NH, NB), block 256. KV tile cached in smem.
// ---------------------------------------------------------------------------
__global__ void __launch_bounds__(256)
msg_kernel()
{
    const int n = blockIdx.z, h = blockIdx.y, lt = blockIdx.x;
    __shared__ float KVs[HD][HD];
    __shared__ float Kss[HD];
    __shared__ float Qs[4][HD];

    const int tid = threadIdx.x;
    const size_t kvbase = (size_t)(n * NH + h) * HD * HD;
    for (int idx = tid; idx < HD * HD; idx += 256)
        KVs[idx >> 6][idx & 63] = g_KV[kvbase + idx];
    if (tid < HD) Kss[tid] = g_Ks[(n * NH + h) * HD + tid];
    __syncthreads();

    const int v  = tid & 63;
    const int ls = tid >> 6;            // 0..3

    for (int it = 0; it < 16; it++) {
        const int l = lt * 64 + it * 4 + ls;
        const size_t qbase = ((size_t)(n * LL + l)) * CC + h * HD;
        Qs[ls][v] = g_Q[qbase + v];
        __syncthreads();

        float zden = EPS_Z;
        float acc  = 0.f;
#pragma unroll
        for (int d = 0; d < HD; d++) {
            const float q = Qs[ls][d];
            zden = fmaf(q, Kss[d], zden);
            acc  = fmaf(q, KVs[d][v], acc);
        }
        g_Msg[qbase + v] = (float)SS * acc / zden;
        __syncthreads();
    }
}

// ---------------------------------------------------------------------------
// Block reduction helper (256 threads)
// ---------------------------------------------------------------------------
__device__ __forceinline__ float block_reduce_sum(float v)
{
    __shared__ float red[8];
    const int lane = threadIdx.x & 31, w = threadIdx.x >> 5;
#pragma unroll
    for (int o = 16; o; o >>= 1) v += __shfl_down_sync(0xffffffffu, v, o);
    if (lane == 0) red[w] = v;
    __syncthreads();
    float t = (threadIdx.x < 8) ? red[threadIdx.x] : 0.f;
    if (w == 0) {
#pragma unroll
        for (int o = 4; o; o >>= 1) t += __shfl_down_sync(0xffu, t, o);
        if (lane == 0) red[0] = t;
    }
    __syncthreads();
    float r = red[0];
    __syncthreads();
    return r;
}

// ---------------------------------------------------------------------------
// LN(M1) with (g1,b1), write H0 = concat(x, ln) per row. One block per row.
// ---------------------------------------------------------------------------
__global__ void __launch_bounds__(256)
ln_concat_kernel(const float* __restrict__ x,
                 const float* __restrict__ g, const float* __restrict__ b)
{
    const int row = blockIdx.x;
    __shared__ float buf[CC];
    const float* mr = g_M1 + (size_t)row * CC;
    const int tid = threadIdx.x;

    float s = 0.f;
    for (int c = tid; c < CC; c += 256) { float v = mr[c]; buf[c] = v; s += v; }
    const float mean = block_reduce_sum(s) * (1.f / CC);

    float vs = 0.f;
    for (int c = tid; c < CC; c += 256) { float d = buf[c] - mean; vs += d * d; }
    const float var  = block_reduce_sum(vs) * (1.f / CC);
    const float rstd = rsqrtf(var + LN_EPS);

    float* H = g_H0 + (size_t)row * C2;
    for (int c = tid; c < CC; c += 256) {
        H[c]      = x[(size_t)row * CC + c];
        H[CC + c] = (buf[c] - mean) * rstd * g[c] + b[c];
    }
}

// ---------------------------------------------------------------------------
// out = x + LN(M2) with (g2,b2). One block per row.
// ---------------------------------------------------------------------------
__global__ void __launch_bounds__(256)
ln_add_kernel(const float* __restrict__ x,
              const float* __restrict__ g, const float* __restrict__ b,
              float* __restrict__ out)
{
    const int row = blockIdx.x;
    __shared__ float buf[CC];
    const float* mr = g_M2 + (size_t)row * CC;
    const int tid = threadIdx.x;

    float s = 0.f;
    for (int c = tid; c < CC; c += 256) { float v = mr[c]; buf[c] = v; s += v; }
    const float mean = block_reduce_sum(s) * (1.f / CC);

    float vs = 0.f;
    for (int c = tid; c < CC; c += 256) { float d = buf[c] - mean; vs += d * d; }
    const float var  = block_reduce_sum(vs) * (1.f / CC);
    const float rstd = rsqrtf(var + LN_EPS);

    for (int c = tid; c < CC; c += 256) {
        out[(size_t)row * CC + c] =
            x[(size_t)row * CC + c] + (buf[c] - mean) * rstd * g[c] + b[c];
    }
}

// ---------------------------------------------------------------------------
// Launcher
// ---------------------------------------------------------------------------
extern "C" void kernel_launch(void* const* d_in, const int* in_sizes, int n_in,
                              void* d_out, int out_size)
{
    const float* x  = (const float*)d_in[0];
    const float* y  = (const float*)d_in[1];
    const float* Wq = (const float*)d_in[2];
    const float* Wk = (const float*)d_in[3];
    const float* Wv = (const float*)d_in[4];
    const float* Wm = (const float*)d_in[5];
    const float* W1 = (const float*)d_in[6];
    const float* W2 = (const float*)d_in[7];
    const float* g1 = (const float*)d_in[8];
    const float* b1 = (const float*)d_in[9];
    const float* g2 = (const float*)d_in[10];
    const float* b2 = (const float*)d_in[11];
    float* out = (float*)d_out;

    float* pQ;  cudaGetSymbolAddress((void**)&pQ,  g_Q);
    float* pK;  cudaGetSymbolAddress((void**)&pK,  g_K);
    float* pV;  cudaGetSymbolAddress((void**)&pV,  g_V);
    float* pMsg; cudaGetSymbolAddress((void**)&pMsg, g_Msg);
    float* pM1; cudaGetSymbolAddress((void**)&pM1, g_M1);
    float* pH0; cudaGetSymbolAddress((void**)&pH0, g_H0);
    float* pH1; cudaGetSymbolAddress((void**)&pH1, g_H1);
    float* pM2; cudaGetSymbolAddress((void**)&pM2, g_M2);

    const dim3 gP(CC / BN, NTOK / BM);    // 4 x 128 (C=512 outputs)
    const dim3 gW1(C2 / BN, NTOK / BM);   // 8 x 128
    // Projections with fused feature map / scaling
    sgemm_nt<1><<<gP, 256>>>(x, Wq, pQ, NTOK, CC, CC, 1.f);
    sgemm_nt<1><<<gP, 256>>>(y, Wk, pK, NTOK, CC, CC, 1.f);
    sgemm_nt<0><<<gP, 256>>>(y, Wv, pV, NTOK, CC, CC, 1.f / (float)SS);

    zero_kv_kernel<<<(NB * NH * HD * HD + 255) / 256, 256>>>();
    kv_kernel<<<dim3(KV_SPLIT, NH, NB), 256>>>();
    msg_kernel<<<dim3(LL / 64, NH, NB), 256>>>();

    sgemm_nt<0><<<gP, 256>>>(pMsg, Wm, pM1, NTOK, CC, CC, 1.f);
    ln_concat_kernel<<<NTOK, 256>>>(x, g1, b1);
    sgemm_nt<2><<<gW1, 256>>>(pH0, W1, pH1, NTOK, C2, C2, 1.f);
    sgemm_nt<0><<<gP, 256>>>(pH1, W2, pM2, NTOK, CC, C2, 1.f);
    ln_add_kernel<<<NTOK, 256>>>(x, g2, b2, out);
}

// round 4
// speedup vs baseline: 2.0509x; 2.0509x over previous
#include <cuda_runtime.h>
#include <cuda_bf16.h>
#include <math.h>
#include <stdint.h>

// ---------------------------------------------------------------------------
// Problem constants
// ---------------------------------------------------------------------------
#define NB   4
#define LL   4096
#define SEQS 4096
#define CC   512
#define NH   8
#define HD   64
#define C2   1024
#define NTOK (NB * LL)          // 16384
#define EPS_Z 1e-6f
#define LN_EPS 1e-5f

// ---------------------------------------------------------------------------
// Scratch (device globals; no allocation allowed)
// ---------------------------------------------------------------------------
__device__ __align__(16) float g_Q [(size_t)NTOK * CC];
__device__ __align__(16) float g_K [(size_t)NTOK * CC];
__device__ __align__(16) float g_V [(size_t)NTOK * CC];
__device__ __align__(16) float g_KV[NB * NH * HD * HD];
__device__ __align__(16) float g_Ks[NB * NH * HD];
__device__ __align__(16) float g_M1[(size_t)NTOK * CC];
__device__ __align__(16) float g_M2[(size_t)NTOK * CC];

// split bf16 (hi/lo) buffers
__device__ __align__(16) __nv_bfloat16 g_xh[(size_t)NTOK * CC], g_xl[(size_t)NTOK * CC];
__device__ __align__(16) __nv_bfloat16 g_yh[(size_t)NTOK * CC], g_yl[(size_t)NTOK * CC];
__device__ __align__(16) __nv_bfloat16 g_Wqh[CC * CC], g_Wql[CC * CC];
__device__ __align__(16) __nv_bfloat16 g_Wkh[CC * CC], g_Wkl[CC * CC];
__device__ __align__(16) __nv_bfloat16 g_Wvh[CC * CC], g_Wvl[CC * CC];
__device__ __align__(16) __nv_bfloat16 g_Wmh[CC * CC], g_Wml[CC * CC];
__device__ __align__(16) __nv_bfloat16 g_W1h[C2 * C2], g_W1l[C2 * C2];
__device__ __align__(16) __nv_bfloat16 g_W2h[CC * C2], g_W2l[CC * C2];
__device__ __align__(16) __nv_bfloat16 g_Mh [(size_t)NTOK * CC], g_Ml [(size_t)NTOK * CC];
__device__ __align__(16) __nv_bfloat16 g_H0h[(size_t)NTOK * C2], g_H0l[(size_t)NTOK * C2];
__device__ __align__(16) __nv_bfloat16 g_H1h[(size_t)NTOK * C2], g_H1l[(size_t)NTOK * C2];

// ---------------------------------------------------------------------------
// PTX helpers (sm_80-era: cp.async, ldmatrix, mma.sync — all OK on compute_100)
// ---------------------------------------------------------------------------
__device__ __forceinline__ uint32_t smem_u32(const void* p)
{
    uint32_t a;
    asm("{ .reg .u64 t; cvta.to.shared.u64 t, %1; cvt.u32.u64 %0, t; }"
        : "=r"(a) : "l"(p));
    return a;
}

__device__ __forceinline__ void cpasync16(uint32_t dst, const void* src)
{
    asm volatile("cp.async.cg.shared.global [%0], [%1], 16;"
                 :: "r"(dst), "l"(src) : "memory");
}
__device__ __forceinline__ void cp_commit()
{
    asm volatile("cp.async.commit_group;" ::: "memory");
}
template <int N>
__device__ __forceinline__ void cp_wait()
{
    asm volatile("cp.async.wait_group %0;" :: "n"(N) : "memory");
}

__device__ __forceinline__ void ldm_x4(uint32_t& r0, uint32_t& r1,
                                       uint32_t& r2, uint32_t& r3, uint32_t a)
{
    asm volatile("ldmatrix.sync.aligned.m8n8.x4.shared.b16 {%0,%1,%2,%3}, [%4];"
                 : "=r"(r0), "=r"(r1), "=r"(r2), "=r"(r3) : "r"(a));
}

__device__ __forceinline__ void mma16816(float* c, const uint32_t* a,
                                         const uint32_t* b)
{
    asm volatile(
        "mma.sync.aligned.m16n8k16.row.col.f32.bf16.bf16.f32 "
        "{%0,%1,%2,%3}, {%4,%5,%6,%7}, {%8,%9}, {%0,%1,%2,%3};"
        : "+f"(c[0]), "+f"(c[1]), "+f"(c[2]), "+f"(c[3])
        : "r"(a[0]), "r"(a[1]), "r"(a[2]), "r"(a[3]), "r"(b[0]), "r"(b[1]));
}

// ---------------------------------------------------------------------------
// Split fp32 -> bf16 hi/lo
// ---------------------------------------------------------------------------
__global__ void __launch_bounds__(256)
split_f32(const float* __restrict__ in, __nv_bfloat16* __restrict__ hi,
          __nv_bfloat16* __restrict__ lo, int n4)
{
    int i = blockIdx.x * blockDim.x + threadIdx.x;
    if (i >= n4) return;
    float4 v = ((const float4*)in)[i];
    __nv_bfloat16 h0 = __float2bfloat16(v.x);
    __nv_bfloat16 h1 = __float2bfloat16(v.y);
    __nv_bfloat16 h2 = __float2bfloat16(v.z);
    __nv_bfloat16 h3 = __float2bfloat16(v.w);
    __nv_bfloat16 l0 = __float2bfloat16(v.x - __bfloat162float(h0));
    __nv_bfloat16 l1 = __float2bfloat16(v.y - __bfloat162float(h1));
    __nv_bfloat16 l2 = __float2bfloat16(v.z - __bfloat162float(h2));
    __nv_bfloat16 l3 = __float2bfloat16(v.w - __bfloat162float(h3));
    ((__nv_bfloat162*)hi)[i * 2 + 0] = __nv_bfloat162(h0, h1);
    ((__nv_bfloat162*)hi)[i * 2 + 1] = __nv_bfloat162(h2, h3);
    ((__nv_bfloat162*)lo)[i * 2 + 0] = __nv_bfloat162(l0, l1);
    ((__nv_bfloat162*)lo)[i * 2 + 1] = __nv_bfloat162(l2, l3);
}

// ---------------------------------------------------------------------------
// Split-bf16 HMMA GEMM.
// C[m,n] = epi( scale * sum_k A[m,k]*B[n,k] )  A=[M,K], B=[N,K] hi/lo bf16.
// Tile 128x128, BK=32 fp32-K per chunk, cp.async double buffer.
// 8 warps in 2x4 grid, warp tile 64x32 (4x4 m16n8k16 mmas).
// 3 passes per chunk: hi*hi, hi*lo, lo*hi.
// smem row = 32 bf16 (64B) + 16B pad = 80B -> conflict-free ldmatrix.
// EPI: 0 = scale -> f32, 1 = elu+1 -> f32, 2 = relu -> bf16 hi/lo
// ---------------------------------------------------------------------------
#define ROWB  80
#define MATB  (128 * ROWB)      // 10240 B per matrix-part tile
#define STAGEB (4 * MATB)       // 40960 B per stage (Ah,Al,Bh,Bl)
#define SMEM_GEMM (2 * STAGEB)  // 81920 B

template <int EPI>
__global__ void __launch_bounds__(256)
hmma_gemm(const __nv_bfloat16* __restrict__ Ah, const __nv_bfloat16* __restrict__ Al,
          const __nv_bfloat16* __restrict__ Bh, const __nv_bfloat16* __restrict__ Bl,
          float* __restrict__ Cf, __nv_bfloat16* __restrict__ Ch,
          __nv_bfloat16* __restrict__ Cl, int N, int K, float scale)
{
    extern __shared__ __align__(16) uint8_t dynsm[];
    const uint32_t sbase = smem_u32(dynsm);

    const int tid  = threadIdx.x;
    const int wid  = tid >> 5;
    const int lane = tid & 31;
    const int wr   = wid >> 2;       // 0..1  (m)
    const int wc   = wid & 3;        // 0..3  (n)
    const int bx   = blockIdx.x;
    const int by   = blockIdx.y;

    // ---- cp.async geometry: 8 x 16B per thread per stage
    const int row0 = tid >> 2;               // 0..63
    const int cb   = (tid & 3) * 16;         // byte col within 64B data region
    const size_t K2 = (size_t)K * 2;

    const char* gAh0 = (const char*)Ah + (size_t)(by * 128 + row0) * K2 + cb;
    const char* gAl0 = (const char*)Al + (size_t)(by * 128 + row0) * K2 + cb;
    const char* gBh0 = (const char*)Bh + (size_t)(bx * 128 + row0) * K2 + cb;
    const char* gBl0 = (const char*)Bl + (size_t)(bx * 128 + row0) * K2 + cb;
    const size_t rstep = 64 * K2;

    const uint32_t dA0 = (uint32_t)(row0 * ROWB + cb);
    const uint32_t dA1 = (uint32_t)((row0 + 64) * ROWB + cb);

    auto issue = [&](int stage, int chunk) {
        const uint32_t s = sbase + stage * STAGEB;
        const size_t o  = (size_t)chunk * 64;
        cpasync16(s + 0 * MATB + dA0, gAh0 + o);
        cpasync16(s + 0 * MATB + dA1, gAh0 + o + rstep);
        cpasync16(s + 1 * MATB + dA0, gAl0 + o);
        cpasync16(s + 1 * MATB + dA1, gAl0 + o + rstep);
        cpasync16(s + 2 * MATB + dA0, gBh0 + o);
        cpasync16(s + 2 * MATB + dA1, gBh0 + o + rstep);
        cpasync16(s + 3 * MATB + dA0, gBl0 + o);
        cpasync16(s + 3 * MATB + dA1, gBl0 + o + rstep);
        cp_commit();
    };

    // ---- ldmatrix lane addressing (byte offsets within a matrix-part tile)
    // A: 16x16 tile at (m0, k16): row = m0 + (lane&15), colb = k16*2 + (lane>>4)*16
    const uint32_t aRow = (uint32_t)(wr * 64 + (lane & 15));
    const uint32_t aCol = (uint32_t)((lane >> 4) << 4);
    // B: 16n x 16k tile at (n0, k16): n = n0 + (lane&7) + ((lane>>4)<<3)
    const uint32_t bRow = (uint32_t)(wc * 32 + (lane & 7) + ((lane >> 4) << 3));
    const uint32_t bCol = (uint32_t)(((lane >> 3) & 1) << 4);

    float acc[4][4][4];
#pragma unroll
    for (int i = 0; i < 4; i++)
#pragma unroll
        for (int j = 0; j < 4; j++)
#pragma unroll
            for (int q = 0; q < 4; q++) acc[i][j][q] = 0.f;

    const int nch = K / 32;
    issue(0, 0);

    for (int c = 0; c < nch; c++) {
        if (c + 1 < nch) { issue((c + 1) & 1, c + 1); cp_wait<1>(); }
        else             { cp_wait<0>(); }
        __syncthreads();

        const uint32_t s  = sbase + (c & 1) * STAGEB;
        const uint32_t pAh = s + 0 * MATB, pAl = s + 1 * MATB;
        const uint32_t pBh = s + 2 * MATB, pBl = s + 3 * MATB;

#pragma unroll
        for (int ks = 0; ks < 2; ks++) {
            const uint32_t kb = (uint32_t)(ks * 32);

            uint32_t ah[4][4], bh[2][4];
#pragma unroll
            for (int mi = 0; mi < 4; mi++)
                ldm_x4(ah[mi][0], ah[mi][1], ah[mi][2], ah[mi][3],
                       pAh + (aRow + mi * 16) * ROWB + kb + aCol);
#pragma unroll
            for (int ng = 0; ng < 2; ng++)
                ldm_x4(bh[ng][0], bh[ng][1], bh[ng][2], bh[ng][3],
                       pBh + (bRow + ng * 16) * ROWB + kb + bCol);

#pragma unroll
            for (int mi = 0; mi < 4; mi++)
#pragma unroll
                for (int ni = 0; ni < 4; ni++)
                    mma16816(acc[mi][ni], ah[mi], &bh[ni >> 1][(ni & 1) * 2]);

            uint32_t bl[2][4];
#pragma unroll
            for (int ng = 0; ng < 2; ng++)
                ldm_x4(bl[ng][0], bl[ng][1], bl[ng][2], bl[ng][3],
                       pBl + (bRow + ng * 16) * ROWB + kb + bCol);
#pragma unroll
            for (int mi = 0; mi < 4; mi++)
#pragma unroll
                for (int ni = 0; ni < 4; ni++)
                    mma16816(acc[mi][ni], ah[mi], &bl[ni >> 1][(ni & 1) * 2]);

            uint32_t al[4][4];
#pragma unroll
            for (int mi = 0; mi < 4; mi++)
                ldm_x4(al[mi][0], al[mi][1], al[mi][2], al[mi][3],
                       pAl + (aRow + mi * 16) * ROWB + kb + aCol);
#pragma unroll
            for (int mi = 0; mi < 4; mi++)
#pragma unroll
                for (int ni = 0; ni < 4; ni++)
                    mma16816(acc[mi][ni], al[mi], &bh[ni >> 1][(ni & 1) * 2]);
        }
        __syncthreads();
    }

    // ---- epilogue
#pragma unroll
    for (int mi = 0; mi < 4; mi++) {
#pragma unroll
        for (int ni = 0; ni < 4; ni++) {
            const int r = by * 128 + wr * 64 + mi * 16 + (lane >> 2);
            const int cn = bx * 128 + wc * 32 + ni * 8 + (lane & 3) * 2;
            float v0 = acc[mi][ni][0] * scale;
            float v1 = acc[mi][ni][1] * scale;
            float v2 = acc[mi][ni][2] * scale;
            float v3 = acc[mi][ni][3] * scale;
            if (EPI == 1) {
                v0 = (v0 > 0.f) ? (v0 + 1.f) : expf(v0);
                v1 = (v1 > 0.f) ? (v1 + 1.f) : expf(v1);
                v2 = (v2 > 0.f) ? (v2 + 1.f) : expf(v2);
                v3 = (v3 > 0.f) ? (v3 + 1.f) : expf(v3);
            }
            if (EPI == 2) {
                v0 = fmaxf(v0, 0.f); v1 = fmaxf(v1, 0.f);
                v2 = fmaxf(v2, 0.f); v3 = fmaxf(v3, 0.f);
                __nv_bfloat16 h0 = __float2bfloat16(v0), h1 = __float2bfloat16(v1);
                __nv_bfloat16 h2 = __float2bfloat16(v2), h3 = __float2bfloat16(v3);
                *(__nv_bfloat162*)(Ch + (size_t)r * N + cn) = __nv_bfloat162(h0, h1);
                *(__nv_bfloat162*)(Ch + (size_t)(r + 8) * N + cn) = __nv_bfloat162(h2, h3);
                *(__nv_bfloat162*)(Cl + (size_t)r * N + cn) =
                    __nv_bfloat162(__float2bfloat16(v0 - __bfloat162float(h0)),
                                   __float2bfloat16(v1 - __bfloat162float(h1)));
                *(__nv_bfloat162*)(Cl + (size_t)(r + 8) * N + cn) =
                    __nv_bfloat162(__float2bfloat16(v2 - __bfloat162float(h2)),
                                   __float2bfloat16(v3 - __bfloat162float(h3)));
            } else {
                *(float2*)(Cf + (size_t)r * N + cn) = make_float2(v0, v1);
                *(float2*)(Cf + (size_t)(r + 8) * N + cn) = make_float2(v2, v3);
            }
        }
    }
}

// ---------------------------------------------------------------------------
// Zero KV / Ksum accumulators
// ---------------------------------------------------------------------------
__global__ void zero_kv_kernel()
{
    int i = blockIdx.x * blockDim.x + threadIdx.x;
    if (i < NB * NH * HD * HD) g_KV[i] = 0.f;
    if (i < NB * NH * HD)      g_Ks[i] = 0.f;
}

// ---------------------------------------------------------------------------
// KV[n,h,d,v] = sum_s K[n,s,h,d]*V[n,s,h,v] ; Ksum[n,h,d] = sum_s K[n,s,h,d]
// ---------------------------------------------------------------------------
#define KV_SPLIT 16
__global__ void __launch_bounds__(256)
kv_kernel()
{
    const int n = blockIdx.z, h = blockIdx.y, sp = blockIdx.x;
    const int SPS = SEQS / KV_SPLIT;
    const int s0  = sp * SPS;

    __shared__ float Ksm[16][HD];
    __shared__ float Vsm[16][HD];

    const int tid = threadIdx.x;
    const int d0  = (tid >> 4) * 4;
    const int v0  = (tid & 15) * 4;
    const int lr  = tid >> 4;
    const int lq  = (tid & 15) * 4;

    float acc[4][4];
#pragma unroll
    for (int i = 0; i < 4; i++)
#pragma unroll
        for (int j = 0; j < 4; j++) acc[i][j] = 0.f;
    float ksacc[4] = {0.f, 0.f, 0.f, 0.f};

    for (int sc = 0; sc < SPS; sc += 16) {
        const size_t base = ((size_t)(n * SEQS + s0 + sc + lr)) * CC + h * HD + lq;
        float4 kv4 = *(const float4*)(g_K + base);
        Ksm[lr][lq + 0] = kv4.x; Ksm[lr][lq + 1] = kv4.y;
        Ksm[lr][lq + 2] = kv4.z; Ksm[lr][lq + 3] = kv4.w;
        float4 vv4 = *(const float4*)(g_V + base);
        Vsm[lr][lq + 0] = vv4.x; Vsm[lr][lq + 1] = vv4.y;
        Vsm[lr][lq + 2] = vv4.z; Vsm[lr][lq + 3] = vv4.w;
        __syncthreads();

#pragma unroll
        for (int s = 0; s < 16; s++) {
            float a[4], b[4];
#pragma unroll
            for (int i = 0; i < 4; i++) a[i] = Ksm[s][d0 + i];
#pragma unroll
            for (int j = 0; j < 4; j++) b[j] = Vsm[s][v0 + j];
#pragma unroll
            for (int i = 0; i < 4; i++)
#pragma unroll
                for (int j = 0; j < 4; j++) acc[i][j] = fmaf(a[i], b[j], acc[i][j]);
            if (v0 == 0) {
#pragma unroll
                for (int i = 0; i < 4; i++) ksacc[i] += a[i];
            }
        }
        __syncthreads();
    }

    float* KVp = g_KV + (size_t)(n * NH + h) * HD * HD;
#pragma unroll
    for (int i = 0; i < 4; i++)
#pragma unroll
        for (int j = 0; j < 4; j++)
            atomicAdd(&KVp[(d0 + i) * HD + v0 + j], acc[i][j]);
    if (v0 == 0) {
        float* Kp = g_Ks + (n * NH + h) * HD;
#pragma unroll
        for (int i = 0; i < 4; i++) atomicAdd(&Kp[d0 + i], ksacc[i]);
    }
}

// ---------------------------------------------------------------------------
// message -> bf16 hi/lo (feeds Wm GEMM)
// ---------------------------------------------------------------------------
__global__ void __launch_bounds__(256)
msg_kernel()
{
    const int n = blockIdx.z, h = blockIdx.y, lt = blockIdx.x;
    __shared__ float KVs[HD][HD];
    __shared__ float Kss[HD];
    __shared__ float Qs[4][HD];

    const int tid = threadIdx.x;
    const size_t kvbase = (size_t)(n * NH + h) * HD * HD;
    for (int idx = tid; idx < HD * HD; idx += 256)
        KVs[idx >> 6][idx & 63] = g_KV[kvbase + idx];
    if (tid < HD) Kss[tid] = g_Ks[(n * NH + h) * HD + tid];
    __syncthreads();

    const int v  = tid & 63;
    const int ls = tid >> 6;

    for (int it = 0; it < 16; it++) {
        const int l = lt * 64 + it * 4 + ls;
        const size_t qbase = ((size_t)(n * LL + l)) * CC + h * HD;
        Qs[ls][v] = g_Q[qbase + v];
        __syncthreads();

        float zden = EPS_Z;
        float acc  = 0.f;
#pragma unroll
        for (int d = 0; d < HD; d++) {
            const float q = Qs[ls][d];
            zden = fmaf(q, Kss[d], zden);
            acc  = fmaf(q, KVs[d][v], acc);
        }
        const float r = (float)SEQS * acc / zden;
        __nv_bfloat16 hh = __float2bfloat16(r);
        g_Mh[qbase + v] = hh;
        g_Ml[qbase + v] = __float2bfloat16(r - __bfloat162float(hh));
        __syncthreads();
    }
}

// ---------------------------------------------------------------------------
// Block reduction helper (256 threads)
// ---------------------------------------------------------------------------
__device__ __forceinline__ float block_reduce_sum(float v)
{
    __shared__ float red[8];
    const int lane = threadIdx.x & 31, w = threadIdx.x >> 5;
#pragma unroll
    for (int o = 16; o; o >>= 1) v += __shfl_down_sync(0xffffffffu, v, o);
    if (lane == 0) red[w] = v;
    __syncthreads();
    float t = (threadIdx.x < 8) ? red[threadIdx.x] : 0.f;
    if (w == 0) {
#pragma unroll
        for (int o = 4; o; o >>= 1) t += __shfl_down_sync(0xffu, t, o);
        if (lane == 0) red[0] = t;
    }
    __syncthreads();
    float r = red[0];
    __syncthreads();
    return r;
}

// ---------------------------------------------------------------------------
// LN(M1), H0 = concat(x_split, ln_split) as bf16 hi/lo. One block per row.
// ---------------------------------------------------------------------------
__global__ void __launch_bounds__(256)
ln_concat_kernel(const float* __restrict__ g, const float* __restrict__ b)
{
    const int row = blockIdx.x;
    __shared__ float buf[CC];
    const float* mr = g_M1 + (size_t)row * CC;
    const int tid = threadIdx.x;

    float s = 0.f;
    for (int c = tid; c < CC; c += 256) { float v = mr[c]; buf[c] = v; s += v; }
    const float mean = block_reduce_sum(s) * (1.f / CC);

    float vs = 0.f;
    for (int c = tid; c < CC; c += 256) { float d = buf[c] - mean; vs += d * d; }
    const float var  = block_reduce_sum(vs) * (1.f / CC);
    const float rstd = rsqrtf(var + LN_EPS);

    __nv_bfloat16* Hh = g_H0h + (size_t)row * C2;
    __nv_bfloat16* Hl = g_H0l + (size_t)row * C2;
    for (int c = tid; c < CC; c += 256) {
        Hh[c] = g_xh[(size_t)row * CC + c];
        Hl[c] = g_xl[(size_t)row * CC + c];
        const float lv = (buf[c] - mean) * rstd * g[c] + b[c];
        __nv_bfloat16 h = __float2bfloat16(lv);
        Hh[CC + c] = h;
        Hl[CC + c] = __float2bfloat16(lv - __bfloat162float(h));
    }
}

// ---------------------------------------------------------------------------
// out = x + LN(M2). One block per row.
// ---------------------------------------------------------------------------
__global__ void __launch_bounds__(256)
ln_add_kernel(const float* __restrict__ x,
              const float* __restrict__ g, const float* __restrict__ b,
              float* __restrict__ out)
{
    const int row = blockIdx.x;
    __shared__ float buf[CC];
    const float* mr = g_M2 + (size_t)row * CC;
    const int tid = threadIdx.x;

    float s = 0.f;
    for (int c = tid; c < CC; c += 256) { float v = mr[c]; buf[c] = v; s += v; }
    const float mean = block_reduce_sum(s) * (1.f / CC);

    float vs = 0.f;
    for (int c = tid; c < CC; c += 256) { float d = buf[c] - mean; vs += d * d; }
    const float var  = block_reduce_sum(vs) * (1.f / CC);
    const float rstd = rsqrtf(var + LN_EPS);

    for (int c = tid; c < CC; c += 256) {
        out[(size_t)row * CC + c] =
            x[(size_t)row * CC + c] + (buf[c] - mean) * rstd * g[c] + b[c];
    }
}

// ---------------------------------------------------------------------------
// Launcher
// ---------------------------------------------------------------------------
extern "C" void kernel_launch(void* const* d_in, const int* in_sizes, int n_in,
                              void* d_out, int out_size)
{
    const float* x  = (const float*)d_in[0];
    const float* y  = (const float*)d_in[1];
    const float* Wq = (const float*)d_in[2];
    const float* Wk = (const float*)d_in[3];
    const float* Wv = (const float*)d_in[4];
    const float* Wm = (const float*)d_in[5];
    const float* W1 = (const float*)d_in[6];
    const float* W2 = (const float*)d_in[7];
    const float* g1 = (const float*)d_in[8];
    const float* b1 = (const float*)d_in[9];
    const float* g2 = (const float*)d_in[10];
    const float* b2 = (const float*)d_in[11];
    float* out = (float*)d_out;

    float *pQ, *pK, *pV, *pM1, *pM2;
    cudaGetSymbolAddress((void**)&pQ,  g_Q);
    cudaGetSymbolAddress((void**)&pK,  g_K);
    cudaGetSymbolAddress((void**)&pV,  g_V);
    cudaGetSymbolAddress((void**)&pM1, g_M1);
    cudaGetSymbolAddress((void**)&pM2, g_M2);

    __nv_bfloat16 *xh,*xl,*yh,*yl,*wqh,*wql,*wkh,*wkl,*wvh,*wvl,*wmh,*wml;
    __nv_bfloat16 *w1h,*w1l,*w2h,*w2l,*mh,*ml,*h0h,*h0l,*h1h,*h1l;
    cudaGetSymbolAddress((void**)&xh,  g_xh);  cudaGetSymbolAddress((void**)&xl,  g_xl);
    cudaGetSymbolAddress((void**)&yh,  g_yh);  cudaGetSymbolAddress((void**)&yl,  g_yl);
    cudaGetSymbolAddress((void**)&wqh, g_Wqh); cudaGetSymbolAddress((void**)&wql, g_Wql);
    cudaGetSymbolAddress((void**)&wkh, g_Wkh); cudaGetSymbolAddress((void**)&wkl, g_Wkl);
    cudaGetSymbolAddress((void**)&wvh, g_Wvh); cudaGetSymbolAddress((void**)&wvl, g_Wvl);
    cudaGetSymbolAddress((void**)&wmh, g_Wmh); cudaGetSymbolAddress((void**)&wml, g_Wml);
    cudaGetSymbolAddress((void**)&w1h, g_W1h); cudaGetSymbolAddress((void**)&w1l, g_W1l);
    cudaGetSymbolAddress((void**)&w2h, g_W2h); cudaGetSymbolAddress((void**)&w2l, g_W2l);
    cudaGetSymbolAddress((void**)&mh,  g_Mh);  cudaGetSymbolAddress((void**)&ml,  g_Ml);
    cudaGetSymbolAddress((void**)&h0h, g_H0h); cudaGetSymbolAddress((void**)&h0l, g_H0l);
    cudaGetSymbolAddress((void**)&h1h, g_H1h); cudaGetSymbolAddress((void**)&h1l, g_H1l);

    cudaFuncSetAttribute(hmma_gemm<0>, cudaFuncAttributeMaxDynamicSharedMemorySize, SMEM_GEMM);
    cudaFuncSetAttribute(hmma_gemm<1>, cudaFuncAttributeMaxDynamicSharedMemorySize, SMEM_GEMM);
    cudaFuncSetAttribute(hmma_gemm<2>, cudaFuncAttributeMaxDynamicSharedMemorySize, SMEM_GEMM);

    auto split = [&](const float* in, __nv_bfloat16* hi, __nv_bfloat16* lo, size_t n) {
        int n4 = (int)(n / 4);
        split_f32<<<(n4 + 255) / 256, 256>>>(in, hi, lo, n4);
    };
    split(x,  xh,  xl,  (size_t)NTOK * CC);
    split(y,  yh,  yl,  (size_t)NTOK * CC);
    split(Wq, wqh, wql, (size_t)CC * CC);
    split(Wk, wkh, wkl, (size_t)CC * CC);
    split(Wv, wvh, wvl, (size_t)CC * CC);
    split(Wm, wmh, wml, (size_t)CC * CC);
    split(W1, w1h, w1l, (size_t)C2 * C2);
    split(W2, w2h, w2l, (size_t)CC * C2);

    const dim3 gP (CC / 128, NTOK / 128);   // 4 x 128
    const dim3 gW1(C2 / 128, NTOK / 128);   // 8 x 128

    hmma_gemm<1><<<gP, 256, SMEM_GEMM>>>(xh, xl, wqh, wql, pQ, nullptr, nullptr, CC, CC, 1.f);
    hmma_gemm<1><<<gP, 256, SMEM_GEMM>>>(yh, yl, wkh, wkl, pK, nullptr, nullptr, CC, CC, 1.f);
    hmma_gemm<0><<<gP, 256, SMEM_GEMM>>>(yh, yl, wvh, wvl, pV, nullptr, nullptr, CC, CC,
                                         1.f / (float)SEQS);

    zero_kv_kernel<<<(NB * NH * HD * HD + 255) / 256, 256>>>();
    kv_kernel<<<dim3(KV_SPLIT, NH, NB), 256>>>();
    msg_kernel<<<dim3(LL / 64, NH, NB), 256>>>();

    hmma_gemm<0><<<gP, 256, SMEM_GEMM>>>(mh, ml, wmh, wml, pM1, nullptr, nullptr, CC, CC, 1.f);
    ln_concat_kernel<<<NTOK, 256>>>(g1, b1);
    hmma_gemm<2><<<gW1, 256, SMEM_GEMM>>>(h0h, h0l, w1h, w1l, nullptr, h1h, h1l, C2, C2, 1.f);
    hmma_gemm<0><<<gP, 256, SMEM_GEMM>>>(h1h, h1l, w2h, w2l, pM2, nullptr, nullptr, CC, C2, 1.f);
    ln_add_kernel<<<NTOK, 256>>>(x, g2, b2, out);
}

// round 5
// speedup vs baseline: 2.5400x; 1.2385x over previous
#include <cuda_runtime.h>
#include <cuda_bf16.h>
#include <math.h>
#include <stdint.h>

// ---------------------------------------------------------------------------
// Problem constants
// ---------------------------------------------------------------------------
#define NB   4
#define LL   4096
#define SEQS 4096
#define CC   512
#define NH   8
#define HD   64
#define C2   1024
#define NTOK (NB * LL)          // 16384
#define EPS_Z 1e-6f
#define LN_EPS 1e-5f

// ---------------------------------------------------------------------------
// Scratch (device globals; no allocation allowed)
// ---------------------------------------------------------------------------
__device__ __align__(16) float g_Q [(size_t)NTOK * CC];
__device__ __align__(16) float g_K [(size_t)NTOK * CC];
__device__ __align__(16) float g_V [(size_t)NTOK * CC];
__device__ __align__(16) float g_KV[NB * NH * HD * HD];
__device__ __align__(16) float g_Ks[NB * NH * HD];
__device__ __align__(16) float g_M1[(size_t)NTOK * CC];
__device__ __align__(16) float g_M2[(size_t)NTOK * CC];

// split bf16 (hi/lo) buffers
__device__ __align__(16) __nv_bfloat16 g_xh[(size_t)NTOK * CC], g_xl[(size_t)NTOK * CC];
__device__ __align__(16) __nv_bfloat16 g_yh[(size_t)NTOK * CC], g_yl[(size_t)NTOK * CC];
__device__ __align__(16) __nv_bfloat16 g_Wqh[CC * CC], g_Wql[CC * CC];
__device__ __align__(16) __nv_bfloat16 g_Wkh[CC * CC], g_Wkl[CC * CC];
__device__ __align__(16) __nv_bfloat16 g_Wvh[CC * CC], g_Wvl[CC * CC];
__device__ __align__(16) __nv_bfloat16 g_Wmh[CC * CC], g_Wml[CC * CC];
__device__ __align__(16) __nv_bfloat16 g_W1h[C2 * C2], g_W1l[C2 * C2];
__device__ __align__(16) __nv_bfloat16 g_W2h[CC * C2], g_W2l[CC * C2];
__device__ __align__(16) __nv_bfloat16 g_Mh  [(size_t)NTOK * CC], g_Ml  [(size_t)NTOK * CC];
__device__ __align__(16) __nv_bfloat16 g_mlnh[(size_t)NTOK * CC], g_mlnl[(size_t)NTOK * CC];
__device__ __align__(16) __nv_bfloat16 g_H1h [(size_t)NTOK * C2], g_H1l [(size_t)NTOK * C2];

// ---------------------------------------------------------------------------
// PTX helpers
// ---------------------------------------------------------------------------
__device__ __forceinline__ uint32_t smem_u32(const void* p)
{
    uint32_t a;
    asm("{ .reg .u64 t; cvta.to.shared.u64 t, %1; cvt.u32.u64 %0, t; }"
        : "=r"(a) : "l"(p));
    return a;
}

__device__ __forceinline__ void cpasync16(uint32_t dst, const void* src)
{
    asm volatile("cp.async.cg.shared.global [%0], [%1], 16;"
                 :: "r"(dst), "l"(src) : "memory");
}
__device__ __forceinline__ void cp_commit()
{
    asm volatile("cp.async.commit_group;" ::: "memory");
}
template <int N>
__device__ __forceinline__ void cp_wait()
{
    asm volatile("cp.async.wait_group %0;" :: "n"(N) : "memory");
}

__device__ __forceinline__ void ldm_x4(uint32_t& r0, uint32_t& r1,
                                       uint32_t& r2, uint32_t& r3, uint32_t a)
{
    asm volatile("ldmatrix.sync.aligned.m8n8.x4.shared.b16 {%0,%1,%2,%3}, [%4];"
                 : "=r"(r0), "=r"(r1), "=r"(r2), "=r"(r3) : "r"(a));
}

__device__ __forceinline__ void mma16816(float* c, const uint32_t* a,
                                         const uint32_t* b)
{
    asm volatile(
        "mma.sync.aligned.m16n8k16.row.col.f32.bf16.bf16.f32 "
        "{%0,%1,%2,%3}, {%4,%5,%6,%7}, {%8,%9}, {%0,%1,%2,%3};"
        : "+f"(c[0]), "+f"(c[1]), "+f"(c[2]), "+f"(c[3])
        : "r"(a[0]), "r"(a[1]), "r"(a[2]), "r"(a[3]), "r"(b[0]), "r"(b[1]));
}

// ---------------------------------------------------------------------------
// Mega split: all fp32 -> bf16 hi/lo conversions in ONE launch
// ---------------------------------------------------------------------------
#define NSPLIT 8
struct SplitJobs {
    const float* src[NSPLIT];
    __nv_bfloat16* hi[NSPLIT];
    __nv_bfloat16* lo[NSPLIT];
    int n4[NSPLIT];
    int blkoff[NSPLIT + 1];
};

__global__ void __launch_bounds__(256)
split_all(SplitJobs J)
{
    int b = blockIdx.x;
    int j = 0;
#pragma unroll
    for (int t = 0; t < NSPLIT - 1; t++)
        if (b >= J.blkoff[t + 1]) j = t + 1;
    const int i = (b - J.blkoff[j]) * 256 + threadIdx.x;
    if (i >= J.n4[j]) return;
    float4 v = ((const float4*)J.src[j])[i];
    __nv_bfloat16 h0 = __float2bfloat16(v.x);
    __nv_bfloat16 h1 = __float2bfloat16(v.y);
    __nv_bfloat16 h2 = __float2bfloat16(v.z);
    __nv_bfloat16 h3 = __float2bfloat16(v.w);
    __nv_bfloat16 l0 = __float2bfloat16(v.x - __bfloat162float(h0));
    __nv_bfloat16 l1 = __float2bfloat16(v.y - __bfloat162float(h1));
    __nv_bfloat16 l2 = __float2bfloat16(v.z - __bfloat162float(h2));
    __nv_bfloat16 l3 = __float2bfloat16(v.w - __bfloat162float(h3));
    ((__nv_bfloat162*)J.hi[j])[i * 2 + 0] = __nv_bfloat162(h0, h1);
    ((__nv_bfloat162*)J.hi[j])[i * 2 + 1] = __nv_bfloat162(h2, h3);
    ((__nv_bfloat162*)J.lo[j])[i * 2 + 0] = __nv_bfloat162(l0, l1);
    ((__nv_bfloat162*)J.lo[j])[i * 2 + 1] = __nv_bfloat162(l2, l3);
}

// ---------------------------------------------------------------------------
// Split-bf16 HMMA GEMM, dual A-source (for fused concat in W1).
// C[m,n] = epi( scale * sum_k A[m,k]*B[n,k] )
// A chunks < kSplit come from A1 (row stride sA1b bytes), else from A2.
// Tile 128x128, BK=32 fp32-K per chunk, cp.async double buffer, 8 warps 2x4.
// 3 passes per chunk: hi*hi, lo*hi, hi*lo.
// EPI: 0 = scale -> f32, 1 = elu+1 -> f32, 2 = relu -> bf16 hi/lo
// ---------------------------------------------------------------------------
#define ROWB  80
#define MATB  (128 * ROWB)      // 10240 B
#define STAGEB (4 * MATB)       // 40960 B
#define SMEM_GEMM (2 * STAGEB)  // 81920 B

template <int EPI>
__global__ void __launch_bounds__(256, 2)
hmma_gemm(const __nv_bfloat16* __restrict__ A1h, const __nv_bfloat16* __restrict__ A1l,
          const __nv_bfloat16* __restrict__ A2h, const __nv_bfloat16* __restrict__ A2l,
          const __nv_bfloat16* __restrict__ Bh,  const __nv_bfloat16* __restrict__ Bl,
          float* __restrict__ Cf, __nv_bfloat16* __restrict__ Ch,
          __nv_bfloat16* __restrict__ Cl, int N, int K, int kSplit,
          size_t sA1b, size_t sA2b, float scale)
{
    extern __shared__ __align__(16) uint8_t dynsm[];
    const uint32_t sbase = smem_u32(dynsm);

    const int tid  = threadIdx.x;
    const int wid  = tid >> 5;
    const int lane = tid & 31;
    const int wr   = wid >> 2;
    const int wc   = wid & 3;
    const int bx   = blockIdx.x;
    const int by   = blockIdx.y;

    const int row0 = tid >> 2;
    const int cb   = (tid & 3) * 16;
    const size_t sBb = (size_t)K * 2;

    const char* gA1h = (const char*)A1h + (size_t)(by * 128 + row0) * sA1b + cb;
    const char* gA1l = (const char*)A1l + (size_t)(by * 128 + row0) * sA1b + cb;
    const char* gA2h = (const char*)A2h + (size_t)(by * 128 + row0) * sA2b + cb;
    const char* gA2l = (const char*)A2l + (size_t)(by * 128 + row0) * sA2b + cb;
    const char* gBh0 = (const char*)Bh  + (size_t)(bx * 128 + row0) * sBb + cb;
    const char* gBl0 = (const char*)Bl  + (size_t)(bx * 128 + row0) * sBb + cb;
    const size_t rs1 = 64 * sA1b, rs2 = 64 * sA2b, rsB = 64 * sBb;

    const uint32_t dA0 = (uint32_t)(row0 * ROWB + cb);
    const uint32_t dA1 = (uint32_t)((row0 + 64) * ROWB + cb);

    auto issue = [&](int stage, int chunk) {
        const uint32_t s = sbase + stage * STAGEB;
        const char *ah, *al; size_t o, rs;
        if (chunk < kSplit) { ah = gA1h; al = gA1l; o = (size_t)chunk * 64; rs = rs1; }
        else { ah = gA2h; al = gA2l; o = (size_t)(chunk - kSplit) * 64; rs = rs2; }
        cpasync16(s + 0 * MATB + dA0, ah + o);
        cpasync16(s + 0 * MATB + dA1, ah + o + rs);
        cpasync16(s + 1 * MATB + dA0, al + o);
        cpasync16(s + 1 * MATB + dA1, al + o + rs);
        const size_t ob = (size_t)chunk * 64;
        cpasync16(s + 2 * MATB + dA0, gBh0 + ob);
        cpasync16(s + 2 * MATB + dA1, gBh0 + ob + rsB);
        cpasync16(s + 3 * MATB + dA0, gBl0 + ob);
        cpasync16(s + 3 * MATB + dA1, gBl0 + ob + rsB);
        cp_commit();
    };

    const uint32_t aRow = (uint32_t)(wr * 64 + (lane & 15));
    const uint32_t aCol = (uint32_t)((lane >> 4) << 4);
    const uint32_t bRow = (uint32_t)(wc * 32 + (lane & 7) + ((lane >> 4) << 3));
    const uint32_t bCol = (uint32_t)(((lane >> 3) & 1) << 4);

    float acc[4][4][4];
#pragma unroll
    for (int i = 0; i < 4; i++)
#pragma unroll
        for (int j = 0; j < 4; j++)
#pragma unroll
            for (int q = 0; q < 4; q++) acc[i][j][q] = 0.f;

    const int nch = K / 32;
    issue(0, 0);

    for (int c = 0; c < nch; c++) {
        if (c + 1 < nch) { issue((c + 1) & 1, c + 1); cp_wait<1>(); }
        else             { cp_wait<0>(); }
        __syncthreads();

        const uint32_t s  = sbase + (c & 1) * STAGEB;
        const uint32_t pAh = s + 0 * MATB, pAl = s + 1 * MATB;
        const uint32_t pBh = s + 2 * MATB, pBl = s + 3 * MATB;

#pragma unroll
        for (int ks = 0; ks < 2; ks++) {
            const uint32_t kb = (uint32_t)(ks * 32);

            uint32_t ah[4][4], bh[2][4];
#pragma unroll
            for (int mi = 0; mi < 4; mi++)
                ldm_x4(ah[mi][0], ah[mi][1], ah[mi][2], ah[mi][3],
                       pAh + (aRow + mi * 16) * ROWB + kb + aCol);
#pragma unroll
            for (int ng = 0; ng < 2; ng++)
                ldm_x4(bh[ng][0], bh[ng][1], bh[ng][2], bh[ng][3],
                       pBh + (bRow + ng * 16) * ROWB + kb + bCol);
#pragma unroll
            for (int mi = 0; mi < 4; mi++)
#pragma unroll
                for (int ni = 0; ni < 4; ni++)
                    mma16816(acc[mi][ni], ah[mi], &bh[ni >> 1][(ni & 1) * 2]);

            // lo(A) * hi(B)
#pragma unroll
            for (int mi = 0; mi < 4; mi++) {
                uint32_t al[4];
                ldm_x4(al[0], al[1], al[2], al[3],
                       pAl + (aRow + mi * 16) * ROWB + kb + aCol);
#pragma unroll
                for (int ni = 0; ni < 4; ni++)
                    mma16816(acc[mi][ni], al, &bh[ni >> 1][(ni & 1) * 2]);
            }

            // hi(A) * lo(B)
#pragma unroll
            for (int ng = 0; ng < 2; ng++) {
                uint32_t bl[4];
                ldm_x4(bl[0], bl[1], bl[2], bl[3],
                       pBl + (bRow + ng * 16) * ROWB + kb + bCol);
#pragma unroll
                for (int mi = 0; mi < 4; mi++) {
                    mma16816(acc[mi][ng * 2 + 0], ah[mi], &bl[0]);
                    mma16816(acc[mi][ng * 2 + 1], ah[mi], &bl[2]);
                }
            }
        }
        __syncthreads();
    }

    // ---- epilogue
#pragma unroll
    for (int mi = 0; mi < 4; mi++) {
#pragma unroll
        for (int ni = 0; ni < 4; ni++) {
            const int r = by * 128 + wr * 64 + mi * 16 + (lane >> 2);
            const int cn = bx * 128 + wc * 32 + ni * 8 + (lane & 3) * 2;
            float v0 = acc[mi][ni][0] * scale;
            float v1 = acc[mi][ni][1] * scale;
            float v2 = acc[mi][ni][2] * scale;
            float v3 = acc[mi][ni][3] * scale;
            if (EPI == 1) {
                v0 = (v0 > 0.f) ? (v0 + 1.f) : expf(v0);
                v1 = (v1 > 0.f) ? (v1 + 1.f) : expf(v1);
                v2 = (v2 > 0.f) ? (v2 + 1.f) : expf(v2);
                v3 = (v3 > 0.f) ? (v3 + 1.f) : expf(v3);
            }
            if (EPI == 2) {
                v0 = fmaxf(v0, 0.f); v1 = fmaxf(v1, 0.f);
                v2 = fmaxf(v2, 0.f); v3 = fmaxf(v3, 0.f);
                __nv_bfloat16 h0 = __float2bfloat16(v0), h1 = __float2bfloat16(v1);
                __nv_bfloat16 h2 = __float2bfloat16(v2), h3 = __float2bfloat16(v3);
                *(__nv_bfloat162*)(Ch + (size_t)r * N + cn) = __nv_bfloat162(h0, h1);
                *(__nv_bfloat162*)(Ch + (size_t)(r + 8) * N + cn) = __nv_bfloat162(h2, h3);
                *(__nv_bfloat162*)(Cl + (size_t)r * N + cn) =
                    __nv_bfloat162(__float2bfloat16(v0 - __bfloat162float(h0)),
                                   __float2bfloat16(v1 - __bfloat162float(h1)));
                *(__nv_bfloat162*)(Cl + (size_t)(r + 8) * N + cn) =
                    __nv_bfloat162(__float2bfloat16(v2 - __bfloat162float(h2)),
                                   __float2bfloat16(v3 - __bfloat162float(h3)));
            } else {
                *(float2*)(Cf + (size_t)r * N + cn) = make_float2(v0, v1);
                *(float2*)(Cf + (size_t)(r + 8) * N + cn) = make_float2(v2, v3);
            }
        }
    }
}

// ---------------------------------------------------------------------------
// Zero KV / Ksum accumulators
// ---------------------------------------------------------------------------
__global__ void zero_kv_kernel()
{
    int i = blockIdx.x * blockDim.x + threadIdx.x;
    if (i < NB * NH * HD * HD) g_KV[i] = 0.f;
    if (i < NB * NH * HD)      g_Ks[i] = 0.f;
}

// ---------------------------------------------------------------------------
// KV[n,h,d,v] = sum_s K[n,s,h,d]*V[n,s,h,v] ; Ksum[n,h,d] = sum_s K[n,s,h,d]
// ---------------------------------------------------------------------------
#define KV_SPLIT 16
__global__ void __launch_bounds__(256)
kv_kernel()
{
    const int n = blockIdx.z, h = blockIdx.y, sp = blockIdx.x;
    const int SPS = SEQS / KV_SPLIT;
    const int s0  = sp * SPS;

    __shared__ float Ksm[16][HD];
    __shared__ float Vsm[16][HD];

    const int tid = threadIdx.x;
    const int d0  = (tid >> 4) * 4;
    const int v0  = (tid & 15) * 4;
    const int lr  = tid >> 4;
    const int lq  = (tid & 15) * 4;

    float acc[4][4];
#pragma unroll
    for (int i = 0; i < 4; i++)
#pragma unroll
        for (int j = 0; j < 4; j++) acc[i][j] = 0.f;
    float ksacc[4] = {0.f, 0.f, 0.f, 0.f};

    for (int sc = 0; sc < SPS; sc += 16) {
        const size_t base = ((size_t)(n * SEQS + s0 + sc + lr)) * CC + h * HD + lq;
        float4 kv4 = *(const float4*)(g_K + base);
        Ksm[lr][lq + 0] = kv4.x; Ksm[lr][lq + 1] = kv4.y;
        Ksm[lr][lq + 2] = kv4.z; Ksm[lr][lq + 3] = kv4.w;
        float4 vv4 = *(const float4*)(g_V + base);
        Vsm[lr][lq + 0] = vv4.x; Vsm[lr][lq + 1] = vv4.y;
        Vsm[lr][lq + 2] = vv4.z; Vsm[lr][lq + 3] = vv4.w;
        __syncthreads();

#pragma unroll
        for (int s = 0; s < 16; s++) {
            float a[4], b[4];
#pragma unroll
            for (int i = 0; i < 4; i++) a[i] = Ksm[s][d0 + i];
#pragma unroll
            for (int j = 0; j < 4; j++) b[j] = Vsm[s][v0 + j];
#pragma unroll
            for (int i = 0; i < 4; i++)
#pragma unroll
                for (int j = 0; j < 4; j++) acc[i][j] = fmaf(a[i], b[j], acc[i][j]);
            if (v0 == 0) {
#pragma unroll
                for (int i = 0; i < 4; i++) ksacc[i] += a[i];
            }
        }
        __syncthreads();
    }

    float* KVp = g_KV + (size_t)(n * NH + h) * HD * HD;
#pragma unroll
    for (int i = 0; i < 4; i++)
#pragma unroll
        for (int j = 0; j < 4; j++)
            atomicAdd(&KVp[(d0 + i) * HD + v0 + j], acc[i][j]);
    if (v0 == 0) {
        float* Kp = g_Ks + (n * NH + h) * HD;
#pragma unroll
        for (int i = 0; i < 4; i++) atomicAdd(&Kp[d0 + i], ksacc[i]);
    }
}

// ---------------------------------------------------------------------------
// message: one thread per l-row, KV broadcast from smem, no inner syncs.
// message[l,h,v] = S * (sum_d Q[l,h,d]*KV[d,v]) / (Q . Ksum + eps) -> bf16 hi/lo
// ---------------------------------------------------------------------------
__global__ void __launch_bounds__(128)
msg_kernel()
{
    const int n = blockIdx.z, h = blockIdx.y, lt = blockIdx.x;
    __shared__ float KVs[HD][HD];
    __shared__ float Kss[HD];

    const int tid = threadIdx.x;
    const size_t kvbase = (size_t)(n * NH + h) * HD * HD;
    for (int idx = tid; idx < HD * HD; idx += 128)
        KVs[idx >> 6][idx & 63] = g_KV[kvbase + idx];
    if (tid < HD) Kss[tid] = g_Ks[(n * NH + h) * HD + tid];
    __syncthreads();

    const int l = lt * 128 + tid;
    const size_t qbase = ((size_t)(n * LL + l)) * CC + h * HD;

    float acc[HD];
#pragma unroll
    for (int v = 0; v < HD; v++) acc[v] = 0.f;
    float zden = EPS_Z;

#pragma unroll
    for (int d0 = 0; d0 < HD; d0 += 4) {
        const float4 q4 = *(const float4*)(g_Q + qbase + d0);
        const float qv[4] = {q4.x, q4.y, q4.z, q4.w};
#pragma unroll
        for (int dd = 0; dd < 4; dd++) {
            const float q = qv[dd];
            zden = fmaf(q, Kss[d0 + dd], zden);
#pragma unroll
            for (int v0 = 0; v0 < HD; v0 += 4) {
                const float4 kv = *(const float4*)&KVs[d0 + dd][v0];
                acc[v0 + 0] = fmaf(q, kv.x, acc[v0 + 0]);
                acc[v0 + 1] = fmaf(q, kv.y, acc[v0 + 1]);
                acc[v0 + 2] = fmaf(q, kv.z, acc[v0 + 2]);
                acc[v0 + 3] = fmaf(q, kv.w, acc[v0 + 3]);
            }
        }
    }

    const float zs = (float)SEQS / zden;
#pragma unroll
    for (int v = 0; v < HD; v += 2) {
        const float r0 = acc[v] * zs, r1 = acc[v + 1] * zs;
        const __nv_bfloat16 h0 = __float2bfloat16(r0);
        const __nv_bfloat16 h1 = __float2bfloat16(r1);
        *(__nv_bfloat162*)(g_Mh + qbase + v) = __nv_bfloat162(h0, h1);
        *(__nv_bfloat162*)(g_Ml + qbase + v) =
            __nv_bfloat162(__float2bfloat16(r0 - __bfloat162float(h0)),
                           __float2bfloat16(r1 - __bfloat162float(h1)));
    }
}

// ---------------------------------------------------------------------------
// Block reduction helper (256 threads)
// ---------------------------------------------------------------------------
__device__ __forceinline__ float block_reduce_sum(float v)
{
    __shared__ float red[8];
    const int lane = threadIdx.x & 31, w = threadIdx.x >> 5;
#pragma unroll
    for (int o = 16; o; o >>= 1) v += __shfl_down_sync(0xffffffffu, v, o);
    if (lane == 0) red[w] = v;
    __syncthreads();
    float t = (threadIdx.x < 8) ? red[threadIdx.x] : 0.f;
    if (w == 0) {
#pragma unroll
        for (int o = 4; o; o >>= 1) t += __shfl_down_sync(0xffu, t, o);
        if (lane == 0) red[0] = t;
    }
    __syncthreads();
    float r = red[0];
    __syncthreads();
    return r;
}

// ---------------------------------------------------------------------------
// LN(M1) -> bf16 hi/lo (the "message half" of the concat). One block per row.
// ---------------------------------------------------------------------------
__global__ void __launch_bounds__(256)
ln_split_kernel(const float* __restrict__ g, const float* __restrict__ b)
{
    const int row = blockIdx.x;
    __shared__ float buf[CC];
    const float* mr = g_M1 + (size_t)row * CC;
    const int tid = threadIdx.x;

    float s = 0.f;
    for (int c = tid; c < CC; c += 256) { float v = mr[c]; buf[c] = v; s += v; }
    const float mean = block_reduce_sum(s) * (1.f / CC);

    float vs = 0.f;
    for (int c = tid; c < CC; c += 256) { float d = buf[c] - mean; vs += d * d; }
    const float var  = block_reduce_sum(vs) * (1.f / CC);
    const float rstd = rsqrtf(var + LN_EPS);

    for (int c = tid; c < CC; c += 256) {
        const float lv = (buf[c] - mean) * rstd * g[c] + b[c];
        const __nv_bfloat16 h = __float2bfloat16(lv);
        g_mlnh[(size_t)row * CC + c] = h;
        g_mlnl[(size_t)row * CC + c] = __float2bfloat16(lv - __bfloat162float(h));
    }
}

// ---------------------------------------------------------------------------
// out = x + LN(M2). One block per row.
// ---------------------------------------------------------------------------
__global__ void __launch_bounds__(256)
ln_add_kernel(const float* __restrict__ x,
              const float* __restrict__ g, const float* __restrict__ b,
              float* __restrict__ out)
{
    const int row = blockIdx.x;
    __shared__ float buf[CC];
    const float* mr = g_M2 + (size_t)row * CC;
    const int tid = threadIdx.x;

    float s = 0.f;
    for (int c = tid; c < CC; c += 256) { float v = mr[c]; buf[c] = v; s += v; }
    const float mean = block_reduce_sum(s) * (1.f / CC);

    float vs = 0.f;
    for (int c = tid; c < CC; c += 256) { float d = buf[c] - mean; vs += d * d; }
    const float var  = block_reduce_sum(vs) * (1.f / CC);
    const float rstd = rsqrtf(var + LN_EPS);

    for (int c = tid; c < CC; c += 256) {
        out[(size_t)row * CC + c] =
            x[(size_t)row * CC + c] + (buf[c] - mean) * rstd * g[c] + b[c];
    }
}

// ---------------------------------------------------------------------------
// Launcher
// ---------------------------------------------------------------------------
extern "C" void kernel_launch(void* const* d_in, const int* in_sizes, int n_in,
                              void* d_out, int out_size)
{
    const float* x  = (const float*)d_in[0];
    const float* y  = (const float*)d_in[1];
    const float* Wq = (const float*)d_in[2];
    const float* Wk = (const float*)d_in[3];
    const float* Wv = (const float*)d_in[4];
    const float* Wm = (const float*)d_in[5];
    const float* W1 = (const float*)d_in[6];
    const float* W2 = (const float*)d_in[7];
    const float* g1 = (const float*)d_in[8];
    const float* b1 = (const float*)d_in[9];
    const float* g2 = (const float*)d_in[10];
    const float* b2 = (const float*)d_in[11];
    float* out = (float*)d_out;

    float *pQ, *pM1, *pM2;
    cudaGetSymbolAddress((void**)&pQ,  g_Q);
    float *pK; cudaGetSymbolAddress((void**)&pK, g_K);
    float *pV; cudaGetSymbolAddress((void**)&pV, g_V);
    cudaGetSymbolAddress((void**)&pM1, g_M1);
    cudaGetSymbolAddress((void**)&pM2, g_M2);

    __nv_bfloat16 *xh,*xl,*yh,*yl,*wqh,*wql,*wkh,*wkl,*wvh,*wvl,*wmh,*wml;
    __nv_bfloat16 *w1h,*w1l,*w2h,*w2l,*mh,*ml,*mlnh,*mlnl,*h1h,*h1l;
    cudaGetSymbolAddress((void**)&xh,  g_xh);  cudaGetSymbolAddress((void**)&xl,  g_xl);
    cudaGetSymbolAddress((void**)&yh,  g_yh);  cudaGetSymbolAddress((void**)&yl,  g_yl);
    cudaGetSymbolAddress((void**)&wqh, g_Wqh); cudaGetSymbolAddress((void**)&wql, g_Wql);
    cudaGetSymbolAddress((void**)&wkh, g_Wkh); cudaGetSymbolAddress((void**)&wkl, g_Wkl);
    cudaGetSymbolAddress((void**)&wvh, g_Wvh); cudaGetSymbolAddress((void**)&wvl, g_Wvl);
    cudaGetSymbolAddress((void**)&wmh, g_Wmh); cudaGetSymbolAddress((void**)&wml, g_Wml);
    cudaGetSymbolAddress((void**)&w1h, g_W1h); cudaGetSymbolAddress((void**)&w1l, g_W1l);
    cudaGetSymbolAddress((void**)&w2h, g_W2h); cudaGetSymbolAddress((void**)&w2l, g_W2l);
    cudaGetSymbolAddress((void**)&mh,  g_Mh);  cudaGetSymbolAddress((void**)&ml,  g_Ml);
    cudaGetSymbolAddress((void**)&mlnh,g_mlnh);cudaGetSymbolAddress((void**)&mlnl,g_mlnl);
    cudaGetSymbolAddress((void**)&h1h, g_H1h); cudaGetSymbolAddress((void**)&h1l, g_H1l);

    cudaFuncSetAttribute(hmma_gemm<0>, cudaFuncAttributeMaxDynamicSharedMemorySize, SMEM_GEMM);
    cudaFuncSetAttribute(hmma_gemm<1>, cudaFuncAttributeMaxDynamicSharedMemorySize, SMEM_GEMM);
    cudaFuncSetAttribute(hmma_gemm<2>, cudaFuncAttributeMaxDynamicSharedMemorySize, SMEM_GEMM);

    // ---- one mega split launch
    SplitJobs J;
    const float* srcs[NSPLIT] = {x, y, Wq, Wk, Wv, Wm, W1, W2};
    __nv_bfloat16* his[NSPLIT] = {xh, yh, wqh, wkh, wvh, wmh, w1h, w2h};
    __nv_bfloat16* los[NSPLIT] = {xl, yl, wql, wkl, wvl, wml, w1l, w2l};
    const int n4s[NSPLIT] = {NTOK * CC / 4, NTOK * CC / 4, CC * CC / 4, CC * CC / 4,
                             CC * CC / 4, CC * CC / 4, C2 * C2 / 4, CC * C2 / 4};
    int off = 0;
    for (int j = 0; j < NSPLIT; j++) {
        J.src[j] = srcs[j]; J.hi[j] = his[j]; J.lo[j] = los[j]; J.n4[j] = n4s[j];
        J.blkoff[j] = off;
        off += (n4s[j] + 255) / 256;
    }
    J.blkoff[NSPLIT] = off;
    split_all<<<off, 256>>>(J);

    const dim3 gP (CC / 128, NTOK / 128);
    const dim3 gW1(C2 / 128, NTOK / 128);
    const size_t sC = (size_t)CC * 2, sC2 = (size_t)C2 * 2;

    hmma_gemm<1><<<gP, 256, SMEM_GEMM>>>(xh, xl, xh, xl, wqh, wql,
                                         pQ, nullptr, nullptr, CC, CC, 9999, sC, sC, 1.f);
    hmma_gemm<1><<<gP, 256, SMEM_GEMM>>>(yh, yl, yh, yl, wkh, wkl,
                                         pK, nullptr, nullptr, CC, CC, 9999, sC, sC, 1.f);
    hmma_gemm<0><<<gP, 256, SMEM_GEMM>>>(yh, yl, yh, yl, wvh, wvl,
                                         pV, nullptr, nullptr, CC, CC, 9999, sC, sC,
                                         1.f / (float)SEQS);

    zero_kv_kernel<<<(NB * NH * HD * HD + 255) / 256, 256>>>();
    kv_kernel<<<dim3(KV_SPLIT, NH, NB), 256>>>();
    msg_kernel<<<dim3(LL / 128, NH, NB), 128>>>();

    hmma_gemm<0><<<gP, 256, SMEM_GEMM>>>(mh, ml, mh, ml, wmh, wml,
                                         pM1, nullptr, nullptr, CC, CC, 9999, sC, sC, 1.f);
    ln_split_kernel<<<NTOK, 256>>>(g1, b1);
    // W1: A = [x | LN(msg)] fused via dual source (chunks 0-15 from x, 16-31 from mln)
    hmma_gemm<2><<<gW1, 256, SMEM_GEMM>>>(xh, xl, mlnh, mlnl, w1h, w1l,
                                          nullptr, h1h, h1l, C2, C2, 16, sC, sC, 1.f);
    hmma_gemm<0><<<gP, 256, SMEM_GEMM>>>(h1h, h1l, h1h, h1l, w2h, w2l,
                                         pM2, nullptr, nullptr, CC, C2, 9999, sC2, sC2, 1.f);
    ln_add_kernel<<<NTOK, 256>>>(x, g2, b2, out);
}

// round 6
// speedup vs baseline: 3.1720x; 1.2488x over previous
#include <cuda_runtime.h>
#include <cuda_fp16.h>
#include <math.h>
#include <stdint.h>

// ---------------------------------------------------------------------------
// Problem constants
// ---------------------------------------------------------------------------
#define NB   4
#define LL   4096
#define SEQS 4096
#define CC   512
#define NH   8
#define HD   64
#define C2   1024
#define NTOK (NB * LL)          // 16384
#define EPS_Z 1e-6f
#define LN_EPS 1e-5f

// ---------------------------------------------------------------------------
// Scratch (device globals; no allocation allowed)
// ---------------------------------------------------------------------------
__device__ __align__(16) float g_Q [(size_t)NTOK * CC];
__device__ __align__(16) float g_K [(size_t)NTOK * CC];
__device__ __align__(16) float g_V [(size_t)NTOK * CC];
__device__ __align__(16) float g_KV[NB * NH * HD * HD];
__device__ __align__(16) float g_Ks[NB * NH * HD];
__device__ __align__(16) float g_M1[(size_t)NTOK * CC];
__device__ __align__(16) float g_M2[(size_t)NTOK * CC];

// split fp16 (hi/lo) activations; weights use hi only
__device__ __align__(16) __half g_xh[(size_t)NTOK * CC], g_xl[(size_t)NTOK * CC];
__device__ __align__(16) __half g_yh[(size_t)NTOK * CC], g_yl[(size_t)NTOK * CC];
__device__ __align__(16) __half g_Wqh[CC * CC];
__device__ __align__(16) __half g_Wkh[CC * CC];
__device__ __align__(16) __half g_Wvh[CC * CC];
__device__ __align__(16) __half g_Wmh[CC * CC];
__device__ __align__(16) __half g_W1h[C2 * C2];
__device__ __align__(16) __half g_W2h[CC * C2];
__device__ __align__(16) __half g_Mh  [(size_t)NTOK * CC], g_Ml  [(size_t)NTOK * CC];
__device__ __align__(16) __half g_mlnh[(size_t)NTOK * CC], g_mlnl[(size_t)NTOK * CC];
__device__ __align__(16) __half g_H1h [(size_t)NTOK * C2], g_H1l [(size_t)NTOK * C2];

// ---------------------------------------------------------------------------
// PTX helpers
// ---------------------------------------------------------------------------
__device__ __forceinline__ uint32_t smem_u32(const void* p)
{
    uint32_t a;
    asm("{ .reg .u64 t; cvta.to.shared.u64 t, %1; cvt.u32.u64 %0, t; }"
        : "=r"(a) : "l"(p));
    return a;
}

__device__ __forceinline__ void cpasync16(uint32_t dst, const void* src)
{
    asm volatile("cp.async.cg.shared.global [%0], [%1], 16;"
                 :: "r"(dst), "l"(src) : "memory");
}
__device__ __forceinline__ void cp_commit()
{
    asm volatile("cp.async.commit_group;" ::: "memory");
}
template <int N>
__device__ __forceinline__ void cp_wait()
{
    asm volatile("cp.async.wait_group %0;" :: "n"(N) : "memory");
}

__device__ __forceinline__ void ldm_x4(uint32_t& r0, uint32_t& r1,
                                       uint32_t& r2, uint32_t& r3, uint32_t a)
{
    asm volatile("ldmatrix.sync.aligned.m8n8.x4.shared.b16 {%0,%1,%2,%3}, [%4];"
                 : "=r"(r0), "=r"(r1), "=r"(r2), "=r"(r3) : "r"(a));
}

__device__ __forceinline__ void mma16816(float* c, const uint32_t* a,
                                         const uint32_t* b)
{
    asm volatile(
        "mma.sync.aligned.m16n8k16.row.col.f32.f16.f16.f32 "
        "{%0,%1,%2,%3}, {%4,%5,%6,%7}, {%8,%9}, {%0,%1,%2,%3};"
        : "+f"(c[0]), "+f"(c[1]), "+f"(c[2]), "+f"(c[3])
        : "r"(a[0]), "r"(a[1]), "r"(a[2]), "r"(a[3]), "r"(b[0]), "r"(b[1]));
}

// ---------------------------------------------------------------------------
// Mega split: fp32 -> fp16 hi/lo (lo pointer may equal hi consumerless for W)
// ---------------------------------------------------------------------------
#define NSPLIT 8
struct SplitJobs {
    const float* src[NSPLIT];
    __half* hi[NSPLIT];
    __half* lo[NSPLIT];      // null -> skip lo
    int n4[NSPLIT];
    int blkoff[NSPLIT + 1];
};

__global__ void __launch_bounds__(256)
split_all(SplitJobs J)
{
    int b = blockIdx.x;
    int j = 0;
#pragma unroll
    for (int t = 0; t < NSPLIT - 1; t++)
        if (b >= J.blkoff[t + 1]) j = t + 1;
    const int i = (b - J.blkoff[j]) * 256 + threadIdx.x;
    if (i >= J.n4[j]) return;
    float4 v = ((const float4*)J.src[j])[i];
    __half h0 = __float2half_rn(v.x);
    __half h1 = __float2half_rn(v.y);
    __half h2 = __float2half_rn(v.z);
    __half h3 = __float2half_rn(v.w);
    ((__half2*)J.hi[j])[i * 2 + 0] = __half2(h0, h1);
    ((__half2*)J.hi[j])[i * 2 + 1] = __half2(h2, h3);
    if (J.lo[j]) {
        __half l0 = __float2half_rn(v.x - __half2float(h0));
        __half l1 = __float2half_rn(v.y - __half2float(h1));
        __half l2 = __float2half_rn(v.z - __half2float(h2));
        __half l3 = __float2half_rn(v.w - __half2float(h3));
        ((__half2*)J.lo[j])[i * 2 + 0] = __half2(l0, l1);
        ((__half2*)J.lo[j])[i * 2 + 1] = __half2(l2, l3);
    }
}

// ---------------------------------------------------------------------------
// fp16 2-pass HMMA GEMM, dual A-source (fused concat for W1).
// C[m,n] = epi( scale * sum_k A[m,k]*B[n,k] ),  A split hi/lo (exact),
// B hi only (error ~2^-12). Tile 128x128, BK=32 fp32-K, 3-stage cp.async.
// 8 warps 2x4, warp tile 64x32. Passes: Ah*Bh, Al*Bh.
// EPI: 0 = scale -> f32, 1 = elu+1 -> f32, 2 = relu -> fp16 hi/lo
// ---------------------------------------------------------------------------
#define ROWB   80
#define MATB   (128 * ROWB)       // 10240 B
#define STAGEB (3 * MATB)         // 30720 B (Ah, Al, Bh)
#define NSTG   3
#define SMEM_GEMM (NSTG * STAGEB) // 92160 B

template <int EPI>
__global__ void __launch_bounds__(256, 2)
hmma_gemm(const __half* __restrict__ A1h, const __half* __restrict__ A1l,
          const __half* __restrict__ A2h, const __half* __restrict__ A2l,
          const __half* __restrict__ Bh,
          float* __restrict__ Cf, __half* __restrict__ Ch,
          __half* __restrict__ Cl, int N, int K, int kSplit,
          size_t sA1b, size_t sA2b, float scale)
{
    extern __shared__ __align__(16) uint8_t dynsm[];
    const uint32_t sbase = smem_u32(dynsm);

    const int tid  = threadIdx.x;
    const int wid  = tid >> 5;
    const int lane = tid & 31;
    const int wr   = wid >> 2;
    const int wc   = wid & 3;
    const int bx   = blockIdx.x;
    const int by   = blockIdx.y;

    const int row0 = tid >> 2;
    const int cb   = (tid & 3) * 16;
    const size_t sBb = (size_t)K * 2;

    const char* gA1h = (const char*)A1h + (size_t)(by * 128 + row0) * sA1b + cb;
    const char* gA1l = (const char*)A1l + (size_t)(by * 128 + row0) * sA1b + cb;
    const char* gA2h = (const char*)A2h + (size_t)(by * 128 + row0) * sA2b + cb;
    const char* gA2l = (const char*)A2l + (size_t)(by * 128 + row0) * sA2b + cb;
    const char* gBh0 = (const char*)Bh  + (size_t)(bx * 128 + row0) * sBb + cb;
    const size_t rs1 = 64 * sA1b, rs2 = 64 * sA2b, rsB = 64 * sBb;

    const uint32_t dA0 = (uint32_t)(row0 * ROWB + cb);
    const uint32_t dA1 = (uint32_t)((row0 + 64) * ROWB + cb);

    auto issue = [&](int stage, int chunk) {
        const uint32_t s = sbase + stage * STAGEB;
        const char *ah, *al; size_t o, rs;
        if (chunk < kSplit) { ah = gA1h; al = gA1l; o = (size_t)chunk * 64; rs = rs1; }
        else { ah = gA2h; al = gA2l; o = (size_t)(chunk - kSplit) * 64; rs = rs2; }
        cpasync16(s + 0 * MATB + dA0, ah + o);
        cpasync16(s + 0 * MATB + dA1, ah + o + rs);
        cpasync16(s + 1 * MATB + dA0, al + o);
        cpasync16(s + 1 * MATB + dA1, al + o + rs);
        const size_t ob = (size_t)chunk * 64;
        cpasync16(s + 2 * MATB + dA0, gBh0 + ob);
        cpasync16(s + 2 * MATB + dA1, gBh0 + ob + rsB);
        cp_commit();
    };

    const uint32_t aRow = (uint32_t)(wr * 64 + (lane & 15));
    const uint32_t aCol = (uint32_t)((lane >> 4) << 4);
    const uint32_t bRow = (uint32_t)(wc * 32 + (lane & 7) + ((lane >> 4) << 3));
    const uint32_t bCol = (uint32_t)(((lane >> 3) & 1) << 4);

    float acc[4][4][4];
#pragma unroll
    for (int i = 0; i < 4; i++)
#pragma unroll
        for (int j = 0; j < 4; j++)
#pragma unroll
            for (int q = 0; q < 4; q++) acc[i][j][q] = 0.f;

    const int nch = K / 32;
    issue(0, 0);
    if (nch > 1) issue(1, 1);

    for (int c = 0; c < nch; c++) {
        if (c + 2 < nch) { issue((c + 2) % NSTG, c + 2); cp_wait<2>(); }
        else if (c + 1 < nch) { cp_wait<1>(); }
        else { cp_wait<0>(); }
        __syncthreads();

        const uint32_t s  = sbase + (c % NSTG) * STAGEB;
        const uint32_t pAh = s + 0 * MATB, pAl = s + 1 * MATB, pBh = s + 2 * MATB;

#pragma unroll
        for (int ks = 0; ks < 2; ks++) {
            const uint32_t kb = (uint32_t)(ks * 32);

            uint32_t ah[4][4], bh[2][4];
#pragma unroll
            for (int mi = 0; mi < 4; mi++)
                ldm_x4(ah[mi][0], ah[mi][1], ah[mi][2], ah[mi][3],
                       pAh + (aRow + mi * 16) * ROWB + kb + aCol);
#pragma unroll
            for (int ng = 0; ng < 2; ng++)
                ldm_x4(bh[ng][0], bh[ng][1], bh[ng][2], bh[ng][3],
                       pBh + (bRow + ng * 16) * ROWB + kb + bCol);
#pragma unroll
            for (int mi = 0; mi < 4; mi++)
#pragma unroll
                for (int ni = 0; ni < 4; ni++)
                    mma16816(acc[mi][ni], ah[mi], &bh[ni >> 1][(ni & 1) * 2]);

            // lo(A) * hi(B)
#pragma unroll
            for (int mi = 0; mi < 4; mi++) {
                uint32_t al[4];
                ldm_x4(al[0], al[1], al[2], al[3],
                       pAl + (aRow + mi * 16) * ROWB + kb + aCol);
#pragma unroll
                for (int ni = 0; ni < 4; ni++)
                    mma16816(acc[mi][ni], al, &bh[ni >> 1][(ni & 1) * 2]);
            }
        }
        __syncthreads();
    }

    // ---- epilogue
#pragma unroll
    for (int mi = 0; mi < 4; mi++) {
#pragma unroll
        for (int ni = 0; ni < 4; ni++) {
            const int r = by * 128 + wr * 64 + mi * 16 + (lane >> 2);
            const int cn = bx * 128 + wc * 32 + ni * 8 + (lane & 3) * 2;
            float v0 = acc[mi][ni][0] * scale;
            float v1 = acc[mi][ni][1] * scale;
            float v2 = acc[mi][ni][2] * scale;
            float v3 = acc[mi][ni][3] * scale;
            if (EPI == 1) {
                v0 = (v0 > 0.f) ? (v0 + 1.f) : expf(v0);
                v1 = (v1 > 0.f) ? (v1 + 1.f) : expf(v1);
                v2 = (v2 > 0.f) ? (v2 + 1.f) : expf(v2);
                v3 = (v3 > 0.f) ? (v3 + 1.f) : expf(v3);
            }
            if (EPI == 2) {
                v0 = fmaxf(v0, 0.f); v1 = fmaxf(v1, 0.f);
                v2 = fmaxf(v2, 0.f); v3 = fmaxf(v3, 0.f);
                __half h0 = __float2half_rn(v0), h1 = __float2half_rn(v1);
                __half h2 = __float2half_rn(v2), h3 = __float2half_rn(v3);
                *(__half2*)(Ch + (size_t)r * N + cn) = __half2(h0, h1);
                *(__half2*)(Ch + (size_t)(r + 8) * N + cn) = __half2(h2, h3);
                *(__half2*)(Cl + (size_t)r * N + cn) =
                    __half2(__float2half_rn(v0 - __half2float(h0)),
                            __float2half_rn(v1 - __half2float(h1)));
                *(__half2*)(Cl + (size_t)(r + 8) * N + cn) =
                    __half2(__float2half_rn(v2 - __half2float(h2)),
                            __float2half_rn(v3 - __half2float(h3)));
            } else {
                *(float2*)(Cf + (size_t)r * N + cn) = make_float2(v0, v1);
                *(float2*)(Cf + (size_t)(r + 8) * N + cn) = make_float2(v2, v3);
            }
        }
    }
}

// ---------------------------------------------------------------------------
// Zero KV / Ksum accumulators
// ---------------------------------------------------------------------------
__global__ void zero_kv_kernel()
{
    int i = blockIdx.x * blockDim.x + threadIdx.x;
    if (i < NB * NH * HD * HD) g_KV[i] = 0.f;
    if (i < NB * NH * HD)      g_Ks[i] = 0.f;
}

// ---------------------------------------------------------------------------
// KV[n,h,d,v] = sum_s K[n,s,h,d]*V[n,s,h,v] ; Ksum[n,h,d] = sum_s K[n,s,h,d]
// ---------------------------------------------------------------------------
#define KV_SPLIT 16
__global__ void __launch_bounds__(256)
kv_kernel()
{
    const int n = blockIdx.z, h = blockIdx.y, sp = blockIdx.x;
    const int SPS = SEQS / KV_SPLIT;
    const int s0  = sp * SPS;

    __shared__ float Ksm[16][HD];
    __shared__ float Vsm[16][HD];

    const int tid = threadIdx.x;
    const int d0  = (tid >> 4) * 4;
    const int v0  = (tid & 15) * 4;
    const int lr  = tid >> 4;
    const int lq  = (tid & 15) * 4;

    float acc[4][4];
#pragma unroll
    for (int i = 0; i < 4; i++)
#pragma unroll
        for (int j = 0; j < 4; j++) acc[i][j] = 0.f;
    float ksacc[4] = {0.f, 0.f, 0.f, 0.f};

    for (int sc = 0; sc < SPS; sc += 16) {
        const size_t base = ((size_t)(n * SEQS + s0 + sc + lr)) * CC + h * HD + lq;
        float4 kv4 = *(const float4*)(g_K + base);
        Ksm[lr][lq + 0] = kv4.x; Ksm[lr][lq + 1] = kv4.y;
        Ksm[lr][lq + 2] = kv4.z; Ksm[lr][lq + 3] = kv4.w;
        float4 vv4 = *(const float4*)(g_V + base);
        Vsm[lr][lq + 0] = vv4.x; Vsm[lr][lq + 1] = vv4.y;
        Vsm[lr][lq + 2] = vv4.z; Vsm[lr][lq + 3] = vv4.w;
        __syncthreads();

#pragma unroll
        for (int s = 0; s < 16; s++) {
            float a[4], b[4];
#pragma unroll
            for (int i = 0; i < 4; i++) a[i] = Ksm[s][d0 + i];
#pragma unroll
            for (int j = 0; j < 4; j++) b[j] = Vsm[s][v0 + j];
#pragma unroll
            for (int i = 0; i < 4; i++)
#pragma unroll
                for (int j = 0; j < 4; j++) acc[i][j] = fmaf(a[i], b[j], acc[i][j]);
            if (v0 == 0) {
#pragma unroll
                for (int i = 0; i < 4; i++) ksacc[i] += a[i];
            }
        }
        __syncthreads();
    }

    float* KVp = g_KV + (size_t)(n * NH + h) * HD * HD;
#pragma unroll
    for (int i = 0; i < 4; i++)
#pragma unroll
        for (int j = 0; j < 4; j++)
            atomicAdd(&KVp[(d0 + i) * HD + v0 + j], acc[i][j]);
    if (v0 == 0) {
        float* Kp = g_Ks + (n * NH + h) * HD;
#pragma unroll
        for (int i = 0; i < 4; i++) atomicAdd(&Kp[d0 + i], ksacc[i]);
    }
}

// ---------------------------------------------------------------------------
// message: one thread per l-row, KV broadcast from smem, no inner syncs.
// ---------------------------------------------------------------------------
__global__ void __launch_bounds__(128)
msg_kernel()
{
    const int n = blockIdx.z, h = blockIdx.y, lt = blockIdx.x;
    __shared__ float KVs[HD][HD];
    __shared__ float Kss[HD];

    const int tid = threadIdx.x;
    const size_t kvbase = (size_t)(n * NH + h) * HD * HD;
    for (int idx = tid; idx < HD * HD; idx += 128)
        KVs[idx >> 6][idx & 63] = g_KV[kvbase + idx];
    if (tid < HD) Kss[tid] = g_Ks[(n * NH + h) * HD + tid];
    __syncthreads();

    const int l = lt * 128 + tid;
    const size_t qbase = ((size_t)(n * LL + l)) * CC + h * HD;

    float acc[HD];
#pragma unroll
    for (int v = 0; v < HD; v++) acc[v] = 0.f;
    float zden = EPS_Z;

#pragma unroll
    for (int d0 = 0; d0 < HD; d0 += 4) {
        const float4 q4 = *(const float4*)(g_Q + qbase + d0);
        const float qv[4] = {q4.x, q4.y, q4.z, q4.w};
#pragma unroll
        for (int dd = 0; dd < 4; dd++) {
            const float q = qv[dd];
            zden = fmaf(q, Kss[d0 + dd], zden);
#pragma unroll
            for (int v0 = 0; v0 < HD; v0 += 4) {
                const float4 kv = *(const float4*)&KVs[d0 + dd][v0];
                acc[v0 + 0] = fmaf(q, kv.x, acc[v0 + 0]);
                acc[v0 + 1] = fmaf(q, kv.y, acc[v0 + 1]);
                acc[v0 + 2] = fmaf(q, kv.z, acc[v0 + 2]);
                acc[v0 + 3] = fmaf(q, kv.w, acc[v0 + 3]);
            }
        }
    }

    const float zs = (float)SEQS / zden;
#pragma unroll
    for (int v = 0; v < HD; v += 2) {
        const float r0 = acc[v] * zs, r1 = acc[v + 1] * zs;
        const __half h0 = __float2half_rn(r0);
        const __half h1 = __float2half_rn(r1);
        *(__half2*)(g_Mh + qbase + v) = __half2(h0, h1);
        *(__half2*)(g_Ml + qbase + v) =
            __half2(__float2half_rn(r0 - __half2float(h0)),
                    __float2half_rn(r1 - __half2float(h1)));
    }
}

// ---------------------------------------------------------------------------
// Block reduction helper (256 threads)
// ---------------------------------------------------------------------------
__device__ __forceinline__ float block_reduce_sum(float v)
{
    __shared__ float red[8];
    const int lane = threadIdx.x & 31, w = threadIdx.x >> 5;
#pragma unroll
    for (int o = 16; o; o >>= 1) v += __shfl_down_sync(0xffffffffu, v, o);
    if (lane == 0) red[w] = v;
    __syncthreads();
    float t = (threadIdx.x < 8) ? red[threadIdx.x] : 0.f;
    if (w == 0) {
#pragma unroll
        for (int o = 4; o; o >>= 1) t += __shfl_down_sync(0xffu, t, o);
        if (lane == 0) red[0] = t;
    }
    __syncthreads();
    float r = red[0];
    __syncthreads();
    return r;
}

// ---------------------------------------------------------------------------
// LN(M1) -> fp16 hi/lo (the "message half" of the concat). One block per row.
// ---------------------------------------------------------------------------
__global__ void __launch_bounds__(256)
ln_split_kernel(const float* __restrict__ g, const float* __restrict__ b)
{
    const int row = blockIdx.x;
    __shared__ float buf[CC];
    const float* mr = g_M1 + (size_t)row * CC;
    const int tid = threadIdx.x;

    float s = 0.f;
    for (int c = tid; c < CC; c += 256) { float v = mr[c]; buf[c] = v; s += v; }
    const float mean = block_reduce_sum(s) * (1.f / CC);

    float vs = 0.f;
    for (int c = tid; c < CC; c += 256) { float d = buf[c] - mean; vs += d * d; }
    const float var  = block_reduce_sum(vs) * (1.f / CC);
    const float rstd = rsqrtf(var + LN_EPS);

    for (int c = tid; c < CC; c += 256) {
        const float lv = (buf[c] - mean) * rstd * g[c] + b[c];
        const __half h = __float2half_rn(lv);
        g_mlnh[(size_t)row * CC + c] = h;
        g_mlnl[(size_t)row * CC + c] = __float2half_rn(lv - __half2float(h));
    }
}

// ---------------------------------------------------------------------------
// out = x + LN(M2). One block per row.
// ---------------------------------------------------------------------------
__global__ void __launch_bounds__(256)
ln_add_kernel(const float* __restrict__ x,
              const float* __restrict__ g, const float* __restrict__ b,
              float* __restrict__ out)
{
    const int row = blockIdx.x;
    __shared__ float buf[CC];
    const float* mr = g_M2 + (size_t)row * CC;
    const int tid = threadIdx.x;

    float s = 0.f;
    for (int c = tid; c < CC; c += 256) { float v = mr[c]; buf[c] = v; s += v; }
    const float mean = block_reduce_sum(s) * (1.f / CC);

    float vs = 0.f;
    for (int c = tid; c < CC; c += 256) { float d = buf[c] - mean; vs += d * d; }
    const float var  = block_reduce_sum(vs) * (1.f / CC);
    const float rstd = rsqrtf(var + LN_EPS);

    for (int c = tid; c < CC; c += 256) {
        out[(size_t)row * CC + c] =
            x[(size_t)row * CC + c] + (buf[c] - mean) * rstd * g[c] + b[c];
    }
}

// ---------------------------------------------------------------------------
// Launcher
// ---------------------------------------------------------------------------
extern "C" void kernel_launch(void* const* d_in, const int* in_sizes, int n_in,
                              void* d_out, int out_size)
{
    const float* x  = (const float*)d_in[0];
    const float* y  = (const float*)d_in[1];
    const float* Wq = (const float*)d_in[2];
    const float* Wk = (const float*)d_in[3];
    const float* Wv = (const float*)d_in[4];
    const float* Wm = (const float*)d_in[5];
    const float* W1 = (const float*)d_in[6];
    const float* W2 = (const float*)d_in[7];
    const float* g1 = (const float*)d_in[8];
    const float* b1 = (const float*)d_in[9];
    const float* g2 = (const float*)d_in[10];
    const float* b2 = (const float*)d_in[11];
    float* out = (float*)d_out;

    float *pQ, *pK, *pV, *pM1, *pM2;
    cudaGetSymbolAddress((void**)&pQ,  g_Q);
    cudaGetSymbolAddress((void**)&pK,  g_K);
    cudaGetSymbolAddress((void**)&pV,  g_V);
    cudaGetSymbolAddress((void**)&pM1, g_M1);
    cudaGetSymbolAddress((void**)&pM2, g_M2);

    __half *xh,*xl,*yh,*yl,*wqh,*wkh,*wvh,*wmh,*w1h,*w2h;
    __half *mh,*ml,*mlnh,*mlnl,*h1h,*h1l;
    cudaGetSymbolAddress((void**)&xh,  g_xh);  cudaGetSymbolAddress((void**)&xl,  g_xl);
    cudaGetSymbolAddress((void**)&yh,  g_yh);  cudaGetSymbolAddress((void**)&yl,  g_yl);
    cudaGetSymbolAddress((void**)&wqh, g_Wqh);
    cudaGetSymbolAddress((void**)&wkh, g_Wkh);
    cudaGetSymbolAddress((void**)&wvh, g_Wvh);
    cudaGetSymbolAddress((void**)&wmh, g_Wmh);
    cudaGetSymbolAddress((void**)&w1h, g_W1h);
    cudaGetSymbolAddress((void**)&w2h, g_W2h);
    cudaGetSymbolAddress((void**)&mh,  g_Mh);  cudaGetSymbolAddress((void**)&ml,  g_Ml);
    cudaGetSymbolAddress((void**)&mlnh,g_mlnh);cudaGetSymbolAddress((void**)&mlnl,g_mlnl);
    cudaGetSymbolAddress((void**)&h1h, g_H1h); cudaGetSymbolAddress((void**)&h1l, g_H1l);

    cudaFuncSetAttribute(hmma_gemm<0>, cudaFuncAttributeMaxDynamicSharedMemorySize, SMEM_GEMM);
    cudaFuncSetAttribute(hmma_gemm<1>, cudaFuncAttributeMaxDynamicSharedMemorySize, SMEM_GEMM);
    cudaFuncSetAttribute(hmma_gemm<2>, cudaFuncAttributeMaxDynamicSharedMemorySize, SMEM_GEMM);

    // ---- one mega split launch (weights: hi only)
    SplitJobs J;
    const float* srcs[NSPLIT] = {x, y, Wq, Wk, Wv, Wm, W1, W2};
    __half* his[NSPLIT] = {xh, yh, wqh, wkh, wvh, wmh, w1h, w2h};
    __half* los[NSPLIT] = {xl, yl, nullptr, nullptr, nullptr, nullptr, nullptr, nullptr};
    const int n4s[NSPLIT] = {NTOK * CC / 4, NTOK * CC / 4, CC * CC / 4, CC * CC / 4,
                             CC * CC / 4, CC * CC / 4, C2 * C2 / 4, CC * C2 / 4};
    int off = 0;
    for (int j = 0; j < NSPLIT; j++) {
        J.src[j] = srcs[j]; J.hi[j] = his[j]; J.lo[j] = los[j]; J.n4[j] = n4s[j];
        J.blkoff[j] = off;
        off += (n4s[j] + 255) / 256;
    }
    J.blkoff[NSPLIT] = off;
    split_all<<<off, 256>>>(J);

    const dim3 gP (CC / 128, NTOK / 128);
    const dim3 gW1(C2 / 128, NTOK / 128);
    const size_t sC = (size_t)CC * 2, sC2 = (size_t)C2 * 2;

    hmma_gemm<1><<<gP, 256, SMEM_GEMM>>>(xh, xl, xh, xl, wqh,
                                         pQ, nullptr, nullptr, CC, CC, 9999, sC, sC, 1.f);
    hmma_gemm<1><<<gP, 256, SMEM_GEMM>>>(yh, yl, yh, yl, wkh,
                                         pK, nullptr, nullptr, CC, CC, 9999, sC, sC, 1.f);
    hmma_gemm<0><<<gP, 256, SMEM_GEMM>>>(yh, yl, yh, yl, wvh,
                                         pV, nullptr, nullptr, CC, CC, 9999, sC, sC,
                                         1.f / (float)SEQS);

    zero_kv_kernel<<<(NB * NH * HD * HD + 255) / 256, 256>>>();
    kv_kernel<<<dim3(KV_SPLIT, NH, NB), 256>>>();
    msg_kernel<<<dim3(LL / 128, NH, NB), 128>>>();

    hmma_gemm<0><<<gP, 256, SMEM_GEMM>>>(mh, ml, mh, ml, wmh,
                                         pM1, nullptr, nullptr, CC, CC, 9999, sC, sC, 1.f);
    ln_split_kernel<<<NTOK, 256>>>(g1, b1);
    // W1: A = [x | LN(msg)] fused via dual source (chunks 0-15 from x, 16-31 from mln)
    hmma_gemm<2><<<gW1, 256, SMEM_GEMM>>>(xh, xl, mlnh, mlnl, w1h,
                                          nullptr, h1h, h1l, C2, C2, 16, sC, sC, 1.f);
    hmma_gemm<0><<<gP, 256, SMEM_GEMM>>>(h1h, h1l, h1h, h1l, w2h,
                                         pM2, nullptr, nullptr, CC, C2, 9999, sC2, sC2, 1.f);
    ln_add_kernel<<<NTOK, 256>>>(x, g2, b2, out);
}